// round 2
// baseline (speedup 1.0000x reference)
#include <cuda_runtime.h>

typedef unsigned long long ull;

#define NA    8
#define BATCH 32768
#define DD    128
#define HHH   128
#define AADIM 64
#define EE    32
#define BM    128
#define SA    130   // stride (floats) for sA / sC (8B-aligned rows, bank-safe)
#define SWC   130   // stride for constraint weights

// smem float offsets
#define OFF_SA    0
#define OFF_SC    (BM * SA)                    // 16640
#define OFF_SB    (OFF_SC + BM * SA)           // 33280
#define OFF_SWC   (OFF_SB + 128 * 128)         // 49664
#define OFF_SG    (OFF_SWC + 33 * SWC)         // 53954
#define OFF_CSUM  (OFF_SG + 128)               // 54082
#define OFF_RED   (OFF_CSUM + 128)             // 54210
#define SMEM_FLOATS (OFF_RED + 256)            // 54466
#define SMEM_BYTES (SMEM_FLOATS * 4)           // 217864

__device__ __forceinline__ void fma2(ull& c, ull a, ull b) {
#if __CUDA_ARCH__ >= 1000
    asm("fma.rn.f32x2 %0, %1, %2, %0;" : "+l"(c) : "l"(a), "l"(b));
#else
    float cx = __uint_as_float((unsigned)c), cy = __uint_as_float((unsigned)(c >> 32));
    float ax = __uint_as_float((unsigned)a), ay = __uint_as_float((unsigned)(a >> 32));
    float bx = __uint_as_float((unsigned)b), by = __uint_as_float((unsigned)(b >> 32));
    cx = fmaf(ax, bx, cx); cy = fmaf(ay, by, cy);
    c = ((ull)__float_as_uint(cy) << 32) | (ull)__float_as_uint(cx);
#endif
}

__device__ __forceinline__ float hsum2(ull v) {
    return __uint_as_float((unsigned)v) + __uint_as_float((unsigned)(v >> 32));
}

// one MLP layer: dst[m][h] = relu(src[m][:] @ W + bias[h]); W pre-staged in sB
// (transposed+swizzled: sB[h*128 + ((k + 2*(h>>3)) & 127)] = W[k][h])
__device__ __forceinline__ void mlp_layer128(
    const float* __restrict__ src, const float* __restrict__ sB,
    float* __restrict__ dst, const float* __restrict__ bias,
    int m0, int h0, int tx)
{
    ull acc[8][8];
#pragma unroll
    for (int i = 0; i < 8; i++)
#pragma unroll
        for (int j = 0; j < 8; j++) acc[i][j] = 0ull;

    const float* pa = src + m0 * SA;
    const float* pb = sB + h0 * 128;
    const int rot2 = 2 * tx;   // (h0+j)>>3 == tx for all j in [0,8)

#pragma unroll 4
    for (int kp = 0; kp < 64; kp++) {
        ull a2[8];
#pragma unroll
        for (int i = 0; i < 8; i++)
            a2[i] = *(const ull*)(pa + i * SA + 2 * kp);
        const int col = (2 * kp + rot2) & 127;
        ull b2[8];
#pragma unroll
        for (int j = 0; j < 8; j++)
            b2[j] = *(const ull*)(pb + j * 128 + col);
#pragma unroll
        for (int i = 0; i < 8; i++)
#pragma unroll
            for (int j = 0; j < 8; j++)
                fma2(acc[i][j], a2[i], b2[j]);
    }

    float bj[8];
#pragma unroll
    for (int j = 0; j < 8; j++) bj[j] = __ldg(bias + h0 + j);

#pragma unroll
    for (int i = 0; i < 8; i++) {
#pragma unroll
        for (int j2 = 0; j2 < 4; j2++) {
            float x = fmaxf(hsum2(acc[i][2 * j2])     + bj[2 * j2],     0.f);
            float y = fmaxf(hsum2(acc[i][2 * j2 + 1]) + bj[2 * j2 + 1], 0.f);
            *(float2*)(dst + (m0 + i) * SA + h0 + 2 * j2) = make_float2(x, y);
        }
    }
}

extern "C" __global__ void __launch_bounds__(256, 1)
qatten_kernel(const float* __restrict__ states,
              const float* __restrict__ W1, const float* __restrict__ b1,
              const float* __restrict__ W2, const float* __restrict__ b2,
              const float* __restrict__ W3, const float* __restrict__ b3,
              const float* __restrict__ Ws1, const float* __restrict__ bs1,
              const float* __restrict__ Ws2, const float* __restrict__ bs2,
              const float* __restrict__ Wc1, const float* __restrict__ bc1,
              const float* __restrict__ Wc2, const float* __restrict__ bc2,
              float* __restrict__ out)
{
    extern __shared__ float sm[];
    float* sA    = sm + OFF_SA;
    float* sC    = sm + OFF_SC;
    float* sB    = sm + OFF_SB;
    float* sWc   = sm + OFF_SWC;
    float* sG    = sm + OFF_SG;
    float* sCsum = sm + OFF_CSUM;
    float* sRed  = sm + OFF_RED;

    const int tid = threadIdx.x;
    const int tx = tid & 15, ty = tid >> 4;
    const int m0 = ty * 8, h0 = tx * 8, a0 = tx * 4;
    const int b0 = blockIdx.x * BM;

    // stage shared constraint/scaling weights once: sWc[e][k]=Wc1[k][e], sWc[32][k]=Ws1[k]
    for (int idx = tid * 4; idx < DD * EE; idx += 256 * 4) {
        float4 w = *(const float4*)(Wc1 + idx);
        int k = idx >> 5, e = idx & 31;
        sWc[(e + 0) * SWC + k] = w.x;
        sWc[(e + 1) * SWC + k] = w.y;
        sWc[(e + 2) * SWC + k] = w.z;
        sWc[(e + 3) * SWC + k] = w.w;
    }
    if (tid < 128) sWc[32 * SWC + tid] = __ldg(Ws1 + tid);

    float oacc[8][4];
#pragma unroll
    for (int i = 0; i < 8; i++)
#pragma unroll
        for (int j = 0; j < 4; j++) oacc[i][j] = 0.f;

    for (int n = 0; n < NA; n++) {
        __syncthreads();  // previous agent done with sA/sB (and sWc staged on n==0)

        // ---- load S tile -> sA[m][k] ----
        const float* Sp = states + ((size_t)n * BATCH + b0) * DD;
#pragma unroll
        for (int i = 0; i < 16; i++) {
            int idx = i * 1024 + tid * 4;
            int m = idx >> 7, k = idx & 127;
            float4 v = *(const float4*)(Sp + idx);
            float* p = sA + m * SA + k;
            *(float2*)(p)     = make_float2(v.x, v.y);
            *(float2*)(p + 2) = make_float2(v.z, v.w);
        }
        // ---- load W1 transposed+swizzled -> sB ----
        const float* W1p = W1 + n * DD * HHH;
#pragma unroll
        for (int i = 0; i < 16; i++) {
            int idx = i * 1024 + tid * 4;
            int k = idx >> 7, h = idx & 127;
            float4 w = *(const float4*)(W1p + idx);
            sB[(h + 0) * 128 + ((k + 2 * ((h + 0) >> 3)) & 127)] = w.x;
            sB[(h + 1) * 128 + ((k + 2 * ((h + 1) >> 3)) & 127)] = w.y;
            sB[(h + 2) * 128 + ((k + 2 * ((h + 2) >> 3)) & 127)] = w.z;
            sB[(h + 3) * 128 + ((k + 2 * ((h + 3) >> 3)) & 127)] = w.w;
        }
        __syncthreads();

        // ---- shared constraint + scaling MLPs (read sA, sWc) ----
        {
            const int row = tid >> 1;
            const int half = tid & 1;
            ull ac[16];
#pragma unroll
            for (int e = 0; e < 16; e++) ac[e] = 0ull;
            ull as_ = 0ull;
            const float* pa = sA + row * SA;
            const float* pw = sWc + (half * 16) * SWC;
            const float* ps = sWc + 32 * SWC;
#pragma unroll 2
            for (int kp = 0; kp < 64; kp++) {
                ull a2 = *(const ull*)(pa + 2 * kp);
#pragma unroll
                for (int e = 0; e < 16; e++) {
                    ull w2 = *(const ull*)(pw + e * SWC + 2 * kp);
                    fma2(ac[e], a2, w2);
                }
                if (half == 0) {
                    ull w2 = *(const ull*)(ps + 2 * kp);
                    fma2(as_, a2, w2);
                }
            }
            float cpart = 0.f;
#pragma unroll
            for (int e = 0; e < 16; e++) {
                float c1 = fmaxf(hsum2(ac[e]) + __ldg(bc1 + half * 16 + e), 0.f);
                cpart = fmaf(c1, __ldg(Wc2 + half * 16 + e), cpart);
            }
            sRed[row * 2 + half] = cpart;
            if (half == 0) {
                float s1 = fmaxf(hsum2(as_) + __ldg(bs1), 0.f);
                float s2 = fmaf(s1, __ldg(Ws2), __ldg(bs2));
                sG[row] = 1.f / (1.f + __expf(-s2));
            }
            __syncthreads();
            if (half == 0) {
                float c2 = sRed[row * 2] + sRed[row * 2 + 1] + __ldg(bc2);
                if (n == 0) sCsum[row] = c2; else sCsum[row] += c2;
            }
        }

        // ---- layer 1: sC = relu(sA @ W1 + b1) ----
        mlp_layer128(sA, sB, sC, b1 + n * HHH, m0, h0, tx);
        __syncthreads();

        // ---- load W2 -> sB ----
        const float* W2p = W2 + n * HHH * HHH;
#pragma unroll
        for (int i = 0; i < 16; i++) {
            int idx = i * 1024 + tid * 4;
            int k = idx >> 7, h = idx & 127;
            float4 w = *(const float4*)(W2p + idx);
            sB[(h + 0) * 128 + ((k + 2 * ((h + 0) >> 3)) & 127)] = w.x;
            sB[(h + 1) * 128 + ((k + 2 * ((h + 1) >> 3)) & 127)] = w.y;
            sB[(h + 2) * 128 + ((k + 2 * ((h + 2) >> 3)) & 127)] = w.z;
            sB[(h + 3) * 128 + ((k + 2 * ((h + 3) >> 3)) & 127)] = w.w;
        }
        __syncthreads();

        // ---- layer 2: sA = relu(sC @ W2 + b2) ----
        mlp_layer128(sC, sB, sA, b2 + n * HHH, m0, h0, tx);
        __syncthreads();

        // ---- load W3 (128x64) -> sB ----
        const float* W3p = W3 + n * HHH * AADIM;
#pragma unroll
        for (int i = 0; i < 8; i++) {
            int idx = i * 1024 + tid * 4;
            int k = idx >> 6, a = idx & 63;
            float4 w = *(const float4*)(W3p + idx);
            sB[(a + 0) * 128 + ((k + 2 * ((a + 0) >> 3)) & 127)] = w.x;
            sB[(a + 1) * 128 + ((k + 2 * ((a + 1) >> 3)) & 127)] = w.y;
            sB[(a + 2) * 128 + ((k + 2 * ((a + 2) >> 3)) & 127)] = w.z;
            sB[(a + 3) * 128 + ((k + 2 * ((a + 3) >> 3)) & 127)] = w.w;
        }
        __syncthreads();

        // ---- layer 3 + gated accumulation: oacc += g[m] * (sA @ W3 + b3) ----
        {
            ull acc[8][4];
#pragma unroll
            for (int i = 0; i < 8; i++)
#pragma unroll
                for (int j = 0; j < 4; j++) acc[i][j] = 0ull;
            const float* pa = sA + m0 * SA;
            int colr[4];
#pragma unroll
            for (int j = 0; j < 4; j++) colr[j] = 2 * ((a0 + j) >> 3);
#pragma unroll 4
            for (int kp = 0; kp < 64; kp++) {
                ull a2[8];
#pragma unroll
                for (int i = 0; i < 8; i++)
                    a2[i] = *(const ull*)(pa + i * SA + 2 * kp);
                ull b2[4];
#pragma unroll
                for (int j = 0; j < 4; j++)
                    b2[j] = *(const ull*)(sB + (a0 + j) * 128 + ((2 * kp + colr[j]) & 127));
#pragma unroll
                for (int i = 0; i < 8; i++)
#pragma unroll
                    for (int j = 0; j < 4; j++)
                        fma2(acc[i][j], a2[i], b2[j]);
            }
            const float* b3n = b3 + n * AADIM;
            float bj[4];
#pragma unroll
            for (int j = 0; j < 4; j++) bj[j] = __ldg(b3n + a0 + j);
#pragma unroll
            for (int i = 0; i < 8; i++) {
                float g = sG[m0 + i];
#pragma unroll
                for (int j = 0; j < 4; j++) {
                    float q = hsum2(acc[i][j]) + bj[j];
                    oacc[i][j] = fmaf(g, q, oacc[i][j]);
                }
            }
        }
    }

    __syncthreads();
    // ---- epilogue: out[b][a] = oacc/8 + csum/8 ----
#pragma unroll
    for (int i = 0; i < 8; i++) {
        int m = m0 + i;
        float cs = sCsum[m] * 0.125f;
        float4 v;
        v.x = fmaf(oacc[i][0], 0.125f, cs);
        v.y = fmaf(oacc[i][1], 0.125f, cs);
        v.z = fmaf(oacc[i][2], 0.125f, cs);
        v.w = fmaf(oacc[i][3], 0.125f, cs);
        *(float4*)(out + (size_t)(b0 + m) * AADIM + a0) = v;
    }
}

extern "C" void kernel_launch(void* const* d_in, const int* in_sizes, int n_in,
                              void* d_out, int out_size)
{
    const float* states = (const float*)d_in[0];
    const float* W1  = (const float*)d_in[1];
    const float* b1  = (const float*)d_in[2];
    const float* W2  = (const float*)d_in[3];
    const float* b2  = (const float*)d_in[4];
    const float* W3  = (const float*)d_in[5];
    const float* b3  = (const float*)d_in[6];
    // d_in[7..12]: Wq1,bq1,Wq2,bq2,Wk,bk — dead code (softmax rows sum to 1)
    const float* Ws1 = (const float*)d_in[13];
    const float* bs1 = (const float*)d_in[14];
    const float* Ws2 = (const float*)d_in[15];
    const float* bs2 = (const float*)d_in[16];
    const float* Wc1 = (const float*)d_in[17];
    const float* bc1 = (const float*)d_in[18];
    const float* Wc2 = (const float*)d_in[19];
    const float* bc2 = (const float*)d_in[20];
    float* out = (float*)d_out;

    cudaFuncSetAttribute(qatten_kernel,
                         cudaFuncAttributeMaxDynamicSharedMemorySize, SMEM_BYTES);

    qatten_kernel<<<BATCH / BM, 256, SMEM_BYTES>>>(
        states, W1, b1, W2, b2, W3, b3,
        Ws1, bs1, Ws2, bs2, Wc1, bc1, Wc2, bc2, out);
}

// round 4
// speedup vs baseline: 3.0709x; 3.0709x over previous
#include <cuda_runtime.h>
#include <cstdint>

typedef unsigned u32;
typedef unsigned long long u64;

#define NAGENT 8
#define BATCH  32768
#define BM     128

// ---- scratch: pre-swizzled bf16 weight planes (hi/lo) ----
// per agent: L1 rows[0,128) off 0, L2 rows off 32768, L3 (64 rows) off 65536; agent stride 81920
__device__ __align__(16) unsigned char g_wh[8 * 81920];
__device__ __align__(16) unsigned char g_wl[8 * 81920];
__device__ __align__(16) unsigned char g_axh[48 * 256];
__device__ __align__(16) unsigned char g_axl[48 * 256];

// ---- smem byte offsets ----
#define RA_HI   0
#define RA_LO   32768
#define RB_HI   65536        // also f32 states staging (64KB)
#define RB_LO   98304
#define RW_OFF  131072       // weight hi plane; lo at RW_OFF + R*256
#define RAX_H   196608
#define RAX_L   208896
#define SG_OFF  221184       // gate per row (128 f32)
#define SCS_OFF 221696       // csum per row
#define SMEM_TOTAL 222208

// ======================= helpers =======================
__device__ __forceinline__ u32 smem_u32(const void* p) {
    u32 a; asm("{ .reg .u64 t; cvta.to.shared.u64 t, %1; cvt.u32.u64 %0, t; }" : "=r"(a) : "l"(p));
    return a;
}
__device__ __forceinline__ void cp16(u32 dst, const void* src) {
    asm volatile("cp.async.cg.shared.global [%0], [%1], 16;" :: "r"(dst), "l"(src));
}
__device__ __forceinline__ void cp_commit() { asm volatile("cp.async.commit_group;"); }
template<int N> __device__ __forceinline__ void cp_wait() {
    asm volatile("cp.async.wait_group %0;" :: "n"(N) : "memory");
}
__device__ __forceinline__ u32 pack_bf2(float lo, float hi) {
    u32 r; asm("cvt.rn.bf16x2.f32 %0, %1, %2;" : "=r"(r) : "f"(hi), "f"(lo));
    return r;   // low 16 = lo arg
}
__device__ __forceinline__ float bf_lo(u32 p) { return __uint_as_float(p << 16); }
__device__ __forceinline__ float bf_hi(u32 p) { return __uint_as_float(p & 0xffff0000u); }
__device__ __forceinline__ u32 split_pair(float x, float y, u32& hi) {
    hi = pack_bf2(x, y);
    return pack_bf2(x - bf_lo(hi), y - bf_hi(hi));
}
// plane byte offset: row n, col k (bf16), 256B rows, XOR swizzle on 16B chunks
__device__ __forceinline__ u32 plane_off(int n, int k) {
    int c = k >> 3;
    u32 sw = (u32)(((c ^ n) & 7) | (c & 8));
    return (u32)(n * 256) + (sw << 4) + (u32)((k & 7) * 2);
}
__device__ __forceinline__ void ldm4(u32* a, u32 addr) {
    asm volatile("ldmatrix.sync.aligned.m8n8.x4.shared.b16 {%0,%1,%2,%3}, [%4];"
        : "=r"(a[0]), "=r"(a[1]), "=r"(a[2]), "=r"(a[3]) : "r"(addr));
}
__device__ __forceinline__ void ldm2(u32* b, u32 addr) {
    asm volatile("ldmatrix.sync.aligned.m8n8.x2.shared.b16 {%0,%1}, [%2];"
        : "=r"(b[0]), "=r"(b[1]) : "r"(addr));
}
__device__ __forceinline__ void mma16816(float* d, const u32* a, const u32* b) {
    asm volatile("mma.sync.aligned.m16n8k16.row.col.f32.bf16.bf16.f32 "
        "{%0,%1,%2,%3}, {%4,%5,%6,%7}, {%8,%9}, {%0,%1,%2,%3};"
        : "+f"(d[0]), "+f"(d[1]), "+f"(d[2]), "+f"(d[3])
        : "r"(a[0]), "r"(a[1]), "r"(a[2]), "r"(a[3]), "r"(b[0]), "r"(b[1]));
}

// ======================= warp GEMM tile (3-pass bf16 split) =======================
// C[MF][NF][4] += (Ah+Al)[m0.., K=128] @ (Bh+Bl)[n0.., K=128]^T   (drops lo*lo)
template<int MF, int NF>
__device__ __forceinline__ void gemm_tile(float C[MF][NF][4],
    u32 ah, u32 al, u32 bh, u32 bl, int m0, int n0, int lane)
{
#pragma unroll
    for (int mf = 0; mf < MF; mf++)
#pragma unroll
        for (int nf = 0; nf < NF; nf++)
#pragma unroll
            for (int i = 0; i < 4; i++) C[mf][nf][i] = 0.f;

    const int rA = m0 + ((lane >> 3) & 1) * 8 + (lane & 7);
    const int gA = lane >> 4;
    const int rB = n0 + (lane & 7);
    const int gB = (lane >> 3) & 1;
    const u32 oA = (u32)rA * 256;
    const u32 oB = (u32)rB * 256;

#pragma unroll
    for (int t = 0; t < 8; t++) {
        const int cA = 2 * t + gA;
        const u32 swA = ((u32)(((cA ^ rA) & 7) | (cA & 8))) << 4;
        const int cB = 2 * t + gB;
        const u32 swB = ((u32)(((cB ^ rB) & 7) | (cB & 8))) << 4;

        u32 A[MF][4];
#pragma unroll
        for (int mf = 0; mf < MF; mf++) ldm4(A[mf], ah + oA + swA + mf * 4096);
        u32 Bh_[NF][2], Bl_[NF][2];
#pragma unroll
        for (int nf = 0; nf < NF; nf++) ldm2(Bh_[nf], bh + oB + swB + nf * 2048);
#pragma unroll
        for (int nf = 0; nf < NF; nf++) ldm2(Bl_[nf], bl + oB + swB + nf * 2048);
#pragma unroll
        for (int mf = 0; mf < MF; mf++)
#pragma unroll
            for (int nf = 0; nf < NF; nf++) mma16816(C[mf][nf], A[mf], Bh_[nf]);
#pragma unroll
        for (int mf = 0; mf < MF; mf++)
#pragma unroll
            for (int nf = 0; nf < NF; nf++) mma16816(C[mf][nf], A[mf], Bl_[nf]);
#pragma unroll
        for (int mf = 0; mf < MF; mf++) ldm4(A[mf], al + oA + swA + mf * 4096);
#pragma unroll
        for (int mf = 0; mf < MF; mf++)
#pragma unroll
            for (int nf = 0; nf < NF; nf++) mma16816(C[mf][nf], A[mf], Bh_[nf]);
    }
}

// relu+bias epilogue -> bf16 hi/lo planes
__device__ __forceinline__ void epi_store(float C[4][4][4], u32 dst_hi, u32 dst_lo,
                                          const float* __restrict__ bias,
                                          int m0, int n0, int lane)
{
    const int r = m0 + (lane >> 2);
    const int cq = (lane & 3) * 2;
#pragma unroll
    for (int mf = 0; mf < 4; mf++) {
        int row0 = r + mf * 16, row8 = row0 + 8;
#pragma unroll
        for (int nf = 0; nf < 4; nf++) {
            int col = n0 + nf * 8 + cq;
            float bx = __ldg(bias + col), by = __ldg(bias + col + 1);
            float x0 = fmaxf(C[mf][nf][0] + bx, 0.f);
            float x1 = fmaxf(C[mf][nf][1] + by, 0.f);
            float x2 = fmaxf(C[mf][nf][2] + bx, 0.f);
            float x3 = fmaxf(C[mf][nf][3] + by, 0.f);
            u32 h0; u32 l0 = split_pair(x0, x1, h0);
            u32 h2; u32 l2 = split_pair(x2, x3, h2);
            int c = col >> 3;
            u32 sw0 = (u32)(((c ^ row0) & 7) | (c & 8));
            u32 sw8 = (u32)(((c ^ row8) & 7) | (c & 8));
            u32 o0 = (u32)row0 * 256 + (sw0 << 4) + (u32)(cq * 2);
            u32 o8 = (u32)row8 * 256 + (sw8 << 4) + (u32)(cq * 2);
            asm volatile("st.shared.b32 [%0], %1;" :: "r"(dst_hi + o0), "r"(h0));
            asm volatile("st.shared.b32 [%0], %1;" :: "r"(dst_lo + o0), "r"(l0));
            asm volatile("st.shared.b32 [%0], %1;" :: "r"(dst_hi + o8), "r"(h2));
            asm volatile("st.shared.b32 [%0], %1;" :: "r"(dst_lo + o8), "r"(l2));
        }
    }
}

// ======================= prep kernel: fp32 weights -> swizzled bf16 planes =======================
extern "C" __global__ void __launch_bounds__(256)
prep_kernel(const float* __restrict__ W1, const float* __restrict__ W2,
            const float* __restrict__ W3, const float* __restrict__ Wc1,
            const float* __restrict__ Ws1)
{
    int idx = blockIdx.x * 256 + threadIdx.x;
    if (idx < 81920) {
        int agent = idx / 10240;
        int rem = idx % 10240;
        int row = rem >> 5;
        int k4 = rem & 31;
        const float* src; int n, N; u32 loff;
        if (row < 128)      { src = W1 + agent * 16384; n = row;       N = 128; loff = 0; }
        else if (row < 256) { src = W2 + agent * 16384; n = row - 128; N = 128; loff = 32768; }
        else                { src = W3 + agent * 8192;  n = row - 256; N = 64;  loff = 65536; }
        int k = k4 * 4;
        float w0 = src[(k + 0) * N + n], w1 = src[(k + 1) * N + n];
        float w2 = src[(k + 2) * N + n], w3 = src[(k + 3) * N + n];
        u32 h0; u32 l0 = split_pair(w0, w1, h0);
        u32 h1; u32 l1 = split_pair(w2, w3, h1);
        u32 off = (u32)agent * 81920 + loff + plane_off(n, k);
        *(uint2*)(g_wh + off) = make_uint2(h0, h1);
        *(uint2*)(g_wl + off) = make_uint2(l0, l1);
    } else if (idx < 81920 + 1536) {
        int rem = idx - 81920;
        int row = rem >> 5, k4 = rem & 31;
        int k = k4 * 4;
        float w[4];
#pragma unroll
        for (int i = 0; i < 4; i++) {
            int kk = k + i;
            w[i] = (row < 32) ? __ldg(Wc1 + kk * 32 + row) : (row == 32 ? __ldg(Ws1 + kk) : 0.f);
        }
        u32 h0; u32 l0 = split_pair(w[0], w[1], h0);
        u32 h1; u32 l1 = split_pair(w[2], w[3], h1);
        u32 off = plane_off(row, k);
        *(uint2*)(g_axh + off) = make_uint2(h0, h1);
        *(uint2*)(g_axl + off) = make_uint2(l0, l1);
    }
}

// ======================= main kernel =======================
extern "C" __global__ void __launch_bounds__(256, 1)
qatten_mma(const float* __restrict__ states,
           const float* __restrict__ b1, const float* __restrict__ b2,
           const float* __restrict__ b3,
           const float* __restrict__ bs1, const float* __restrict__ Ws2,
           const float* __restrict__ bs2,
           const float* __restrict__ bc1, const float* __restrict__ Wc2,
           const float* __restrict__ bc2,
           float* __restrict__ out)
{
    extern __shared__ char smem[];
    const u32 sb = smem_u32(smem);
    const int tid = threadIdx.x;
    const int wid = tid >> 5, lane = tid & 31;
    const int b0 = blockIdx.x * BM;

    float* sG   = (float*)(smem + SG_OFF);
    float* sCs  = (float*)(smem + SCS_OFF);

    // main-layer warp tiling
    const int m0 = (wid & 1) * 64;
    const int n0 = (wid >> 1) * 32;     // L1/L2 (N=128)
    const int n0_3 = (wid >> 1) * 16;   // L3 (N=64)
    const int m0_ax = wid * 16;         // aux (M split 8 ways)

    // ---- prologue: stage states(0) f32 -> RB ; W1(0)+aux -> smem ----
    {
        const unsigned char* S0 = (const unsigned char*)(states + (size_t)b0 * 128);
        for (int i = tid * 16; i < 65536; i += 4096) cp16(sb + RB_HI + i, S0 + i);
        cp_commit();                                   // group: states
        for (int i = tid * 16; i < 32768; i += 4096) cp16(sb + RW_OFF + i, g_wh + i);
        for (int i = tid * 16; i < 32768; i += 4096) cp16(sb + RW_OFF + 32768 + i, g_wl + i);
        for (int i = tid * 16; i < 12288; i += 4096) cp16(sb + RAX_H + i, g_axh + i);
        for (int i = tid * 16; i < 12288; i += 4096) cp16(sb + RAX_L + i, g_axl + i);
        cp_commit();                                   // group: W1 + aux
    }

    float oacc[4][2][4];
#pragma unroll
    for (int mf = 0; mf < 4; mf++)
#pragma unroll
        for (int nf = 0; nf < 2; nf++)
#pragma unroll
            for (int i = 0; i < 4; i++) oacc[mf][nf][i] = 0.f;
    float creg0 = 0.f, creg1 = 0.f;

    const float r_bs1 = __ldg(bs1), r_Ws2 = __ldg(Ws2), r_bs2 = __ldg(bs2), r_bc2 = __ldg(bc2);

    for (int n = 0; n < NAGENT; n++) {
        // ---- convert staged f32 states (RB) -> RA bf16 planes ----
        cp_wait<1>();          // states group done (W-group may be pending)
        __syncthreads();
#pragma unroll
        for (int i = 0; i < 16; i++) {
            int idx = tid + 256 * i;
            int m = idx >> 5, c4 = idx & 31;
            float4 v;
            asm volatile("ld.shared.v4.f32 {%0,%1,%2,%3}, [%4];"
                : "=f"(v.x), "=f"(v.y), "=f"(v.z), "=f"(v.w)
                : "r"(sb + RB_HI + m * 512 + c4 * 16));
            u32 h0; u32 l0 = split_pair(v.x, v.y, h0);
            u32 h1; u32 l1 = split_pair(v.z, v.w, h1);
            u32 off = plane_off(m, c4 * 4);
            asm volatile("st.shared.v2.b32 [%0], {%1,%2};" :: "r"(sb + RA_HI + off), "r"(h0), "r"(h1));
            asm volatile("st.shared.v2.b32 [%0], {%1,%2};" :: "r"(sb + RA_LO + off), "r"(l0), "r"(l1));
        }
        cp_wait<0>();          // W1 (+aux on n=0) done
        __syncthreads();

        // ---- aux GEMM (N=40 used) + epilogue: gate + constraint ----
        {
            float Cx[1][5][4];
            gemm_tile<1, 5>(Cx, sb + RA_HI, sb + RA_LO, sb + RAX_H, sb + RAX_L,
                            m0_ax, 0, lane);
            float cp0 = 0.f, cp1 = 0.f;
#pragma unroll
            for (int nf = 0; nf < 4; nf++) {
#pragma unroll
                for (int h = 0; h < 2; h++) {
                    int e = nf * 8 + (lane & 3) * 2 + h;
                    float wc = __ldg(Wc2 + e), bb = __ldg(bc1 + e);
                    cp0 = fmaf(fmaxf(Cx[0][nf][h]     + bb, 0.f), wc, cp0);
                    cp1 = fmaf(fmaxf(Cx[0][nf][2 + h] + bb, 0.f), wc, cp1);
                }
            }
            cp0 += __shfl_xor_sync(0xffffffffu, cp0, 1);
            cp0 += __shfl_xor_sync(0xffffffffu, cp0, 2);
            cp1 += __shfl_xor_sync(0xffffffffu, cp1, 1);
            cp1 += __shfl_xor_sync(0xffffffffu, cp1, 2);
            if ((lane & 3) == 0) {
                creg0 += cp0 + r_bc2;
                creg1 += cp1 + r_bc2;
                float s0 = fmaf(fmaxf(Cx[0][4][0] + r_bs1, 0.f), r_Ws2, r_bs2);
                float s8 = fmaf(fmaxf(Cx[0][4][2] + r_bs1, 0.f), r_Ws2, r_bs2);
                sG[m0_ax + (lane >> 2)]     = 1.f / (1.f + __expf(-s0));
                sG[m0_ax + (lane >> 2) + 8] = 1.f / (1.f + __expf(-s8));
            }
        }

        // ---- L1: RA @ W1 -> RB planes ----
        {
            float C[4][4][4];
            gemm_tile<4, 4>(C, sb + RA_HI, sb + RA_LO, sb + RW_OFF, sb + RW_OFF + 32768,
                            m0, n0, lane);
            __syncthreads();   // all warps done reading RW + RB(staging consumed)
            {   // cp W2 -> RW (overlaps epilogue)
                const unsigned char* src = g_wh + (size_t)n * 81920 + 32768;
                const unsigned char* srl = g_wl + (size_t)n * 81920 + 32768;
                for (int i = tid * 16; i < 32768; i += 4096) cp16(sb + RW_OFF + i, src + i);
                for (int i = tid * 16; i < 32768; i += 4096) cp16(sb + RW_OFF + 32768 + i, srl + i);
                cp_commit();
            }
            epi_store(C, sb + RB_HI, sb + RB_LO, b1 + n * 128, m0, n0, lane);
        }
        cp_wait<0>();
        __syncthreads();

        // ---- L2: RB @ W2 -> RA planes ----
        {
            float C[4][4][4];
            gemm_tile<4, 4>(C, sb + RB_HI, sb + RB_LO, sb + RW_OFF, sb + RW_OFF + 32768,
                            m0, n0, lane);
            __syncthreads();
            {   // cp W3 -> RW
                const unsigned char* src = g_wh + (size_t)n * 81920 + 65536;
                const unsigned char* srl = g_wl + (size_t)n * 81920 + 65536;
                for (int i = tid * 16; i < 16384; i += 4096) cp16(sb + RW_OFF + i, src + i);
                for (int i = tid * 16; i < 16384; i += 4096) cp16(sb + RW_OFF + 16384 + i, srl + i);
                cp_commit();
            }
            epi_store(C, sb + RA_HI, sb + RA_LO, b2 + n * 128, m0, n0, lane);
        }
        cp_wait<0>();
        __syncthreads();

        // ---- L3: RA @ W3 (N=64) -> oacc ----
        {
            float C[4][2][4];
            gemm_tile<4, 2>(C, sb + RA_HI, sb + RA_LO, sb + RW_OFF, sb + RW_OFF + 16384,
                            m0, n0_3, lane);
            __syncthreads();   // done reading RW + RA
            // prefetch states(n+1) -> RB, W1(n+1) -> RW
            if (n < NAGENT - 1) {
                const unsigned char* Sn =
                    (const unsigned char*)(states + ((size_t)(n + 1) * BATCH + b0) * 128);
                for (int i = tid * 16; i < 65536; i += 4096) cp16(sb + RB_HI + i, Sn + i);
                cp_commit();   // states group
                const unsigned char* src = g_wh + (size_t)(n + 1) * 81920;
                const unsigned char* srl = g_wl + (size_t)(n + 1) * 81920;
                for (int i = tid * 16; i < 32768; i += 4096) cp16(sb + RW_OFF + i, src + i);
                for (int i = tid * 16; i < 32768; i += 4096) cp16(sb + RW_OFF + 32768 + i, srl + i);
                cp_commit();   // W1 group
            } else {
                cp_commit(); cp_commit();  // keep group-count invariant
            }
            // epilogue: oacc += g * (C + b3)
            const float* b3n = b3 + n * 64;
            const int r = (lane >> 2);
            const int cq = (lane & 3) * 2;
#pragma unroll
            for (int mf = 0; mf < 4; mf++) {
                int row0 = m0 + mf * 16 + r;
                float g0 = sG[row0], g8 = sG[row0 + 8];
#pragma unroll
                for (int nf = 0; nf < 2; nf++) {
                    int col = n0_3 + nf * 8 + cq;
                    float bx = __ldg(b3n + col), by = __ldg(b3n + col + 1);
                    oacc[mf][nf][0] = fmaf(g0, C[mf][nf][0] + bx, oacc[mf][nf][0]);
                    oacc[mf][nf][1] = fmaf(g0, C[mf][nf][1] + by, oacc[mf][nf][1]);
                    oacc[mf][nf][2] = fmaf(g8, C[mf][nf][2] + bx, oacc[mf][nf][2]);
                    oacc[mf][nf][3] = fmaf(g8, C[mf][nf][3] + by, oacc[mf][nf][3]);
                }
            }
        }
    }

    // ---- final: csum exchange + output ----
    if ((lane & 3) == 0) {
        sCs[m0_ax + (lane >> 2)]     = creg0;
        sCs[m0_ax + (lane >> 2) + 8] = creg1;
    }
    __syncthreads();
    {
        const int r = (lane >> 2);
        const int cq = (lane & 3) * 2;
#pragma unroll
        for (int mf = 0; mf < 4; mf++) {
            int row0 = m0 + mf * 16 + r, row8 = row0 + 8;
            float cs0 = sCs[row0] * 0.125f, cs8 = sCs[row8] * 0.125f;
#pragma unroll
            for (int nf = 0; nf < 2; nf++) {
                int col = n0_3 + nf * 8 + cq;
                float2 v0, v8;
                v0.x = fmaf(oacc[mf][nf][0], 0.125f, cs0);
                v0.y = fmaf(oacc[mf][nf][1], 0.125f, cs0);
                v8.x = fmaf(oacc[mf][nf][2], 0.125f, cs8);
                v8.y = fmaf(oacc[mf][nf][3], 0.125f, cs8);
                *(float2*)(out + (size_t)(b0 + row0) * 64 + col) = v0;
                *(float2*)(out + (size_t)(b0 + row8) * 64 + col) = v8;
            }
        }
    }
}

extern "C" void kernel_launch(void* const* d_in, const int* in_sizes, int n_in,
                              void* d_out, int out_size)
{
    const float* states = (const float*)d_in[0];
    const float* W1  = (const float*)d_in[1];
    const float* b1  = (const float*)d_in[2];
    const float* W2  = (const float*)d_in[3];
    const float* b2  = (const float*)d_in[4];
    const float* W3  = (const float*)d_in[5];
    const float* b3  = (const float*)d_in[6];
    // d_in[7..12]: Wq1,bq1,Wq2,bq2,Wk,bk — dead (softmax rows sum to 1)
    const float* Ws1 = (const float*)d_in[13];
    const float* bs1 = (const float*)d_in[14];
    const float* Ws2 = (const float*)d_in[15];
    const float* bs2 = (const float*)d_in[16];
    const float* Wc1 = (const float*)d_in[17];
    const float* bc1 = (const float*)d_in[18];
    const float* Wc2 = (const float*)d_in[19];
    const float* bc2 = (const float*)d_in[20];
    float* out = (float*)d_out;

    prep_kernel<<<(81920 + 1536 + 255) / 256, 256>>>(W1, W2, W3, Wc1, Ws1);

    cudaFuncSetAttribute(qatten_mma,
                         cudaFuncAttributeMaxDynamicSharedMemorySize, SMEM_TOTAL);
    qatten_mma<<<BATCH / BM, 256, SMEM_TOTAL>>>(
        states, b1, b2, b3, bs1, Ws2, bs2, bc1, Wc2, bc2, out);
}

// round 6
// speedup vs baseline: 3.7786x; 1.2304x over previous
#include <cuda_runtime.h>
#include <cuda_fp16.h>
#include <cstdint>

typedef unsigned u32;

#define NAGENT 8
#define BATCH  32768
#define BM     64

// ---- scratch: pre-swizzled fp16 weights ----
// per agent: L1 (128 rows) off 0, L2 off 32768, L3 (64 rows) off 65536; stride 81920
__device__ __align__(16) unsigned char g_w[8 * 81920];
__device__ __align__(16) unsigned char g_ax[48 * 256];   // aux: Wc1^T rows 0-31, Ws1 row 32, pad

// ---- smem byte offsets (per CTA, ~109 KB -> 2 CTAs/SM) ----
#define RA_HI 0          // 64 rows x 256B fp16 plane
#define RA_LO 16384
#define RB_HI 32768      // also f32 states staging (64 x 512B = 32KB over RB_HI..RB_LO)
#define RB_LO 49152
#define RW    65536      // weights, 176 rows x 256B = 45056 (aux rows 128-175 persist)
#define SGOFF 110592     // gate per row (64 f32)
#define SREDO 110848     // csum partials (64 rows x 2 warps)
#define SMEM_TOTAL 111616

// ======================= helpers =======================
__device__ __forceinline__ u32 smem_u32(const void* p) {
    u32 a; asm("{ .reg .u64 t; cvta.to.shared.u64 t, %1; cvt.u32.u64 %0, t; }" : "=r"(a) : "l"(p));
    return a;
}
__device__ __forceinline__ void cp16(u32 dst, const void* src) {
    asm volatile("cp.async.cg.shared.global [%0], [%1], 16;" :: "r"(dst), "l"(src));
}
__device__ __forceinline__ void cp_commit() { asm volatile("cp.async.commit_group;"); }
template<int N> __device__ __forceinline__ void cp_wait() {
    asm volatile("cp.async.wait_group %0;" :: "n"(N) : "memory");
}
// fp16 split: x = hi + lo (lo itself fp16, residual ~2^-22)
__device__ __forceinline__ u32 split_h(float x, float y, u32& hi) {
    __half2 h = __floats2half2_rn(x, y);           // x -> low half
    hi = *reinterpret_cast<u32*>(&h);
    float rx = x - __half2float(__low2half(h));
    float ry = y - __half2float(__high2half(h));
    __half2 l = __floats2half2_rn(rx, ry);
    return *reinterpret_cast<u32*>(&l);
}
__device__ __forceinline__ u32 pack_h(float x, float y) {
    __half2 h = __floats2half2_rn(x, y);
    return *reinterpret_cast<u32*>(&h);
}
// plane byte offset: row n, half-col k; 256B rows, XOR swizzle on 16B chunks
__device__ __forceinline__ u32 plane_off(int n, int k) {
    int c = k >> 3;
    u32 sw = (u32)(((c ^ n) & 7) | (c & 8));
    return (u32)(n * 256) + (sw << 4) + (u32)((k & 7) * 2);
}
__device__ __forceinline__ void ldm4(u32* a, u32 addr) {
    asm volatile("ldmatrix.sync.aligned.m8n8.x4.shared.b16 {%0,%1,%2,%3}, [%4];"
        : "=r"(a[0]), "=r"(a[1]), "=r"(a[2]), "=r"(a[3]) : "r"(addr));
}
__device__ __forceinline__ void ldm2(u32* b, u32 addr) {
    asm volatile("ldmatrix.sync.aligned.m8n8.x2.shared.b16 {%0,%1}, [%2];"
        : "=r"(b[0]), "=r"(b[1]) : "r"(addr));
}
__device__ __forceinline__ void mma_h(float* d, const u32* a, const u32* b) {
    asm volatile("mma.sync.aligned.m16n8k16.row.col.f32.f16.f16.f32 "
        "{%0,%1,%2,%3}, {%4,%5,%6,%7}, {%8,%9}, {%0,%1,%2,%3};"
        : "+f"(d[0]), "+f"(d[1]), "+f"(d[2]), "+f"(d[3])
        : "r"(a[0]), "r"(a[1]), "r"(a[2]), "r"(a[3]), "r"(b[0]), "r"(b[1]));
}

// ======================= warp GEMM (2-pass fp16 split A, single-plane W) ===========
// C[NF][4] = (Ah + Al)[16 rows @ m0, K=128] @ W[tiles (2j+nw)]^T
template<int NF>
__device__ __forceinline__ void gemm2(float C[NF][4], u32 ah, u32 al, u32 bw,
                                      int m0, int nw, int lane)
{
#pragma unroll
    for (int j = 0; j < NF; j++)
#pragma unroll
        for (int i = 0; i < 4; i++) C[j][i] = 0.f;

    const int rA = m0 + (lane & 7) + ((lane >> 3) & 1) * 8;
    const int gA = lane >> 4;
    const int rBl = lane & 7;
    const int gB = (lane >> 3) & 1;
    const u32 oA = (u32)rA * 256;

#pragma unroll
    for (int t = 0; t < 8; t++) {
        const int cA = 2 * t + gA;
        const u32 swA = ((u32)(((cA ^ rA) & 7) | (cA & 8))) << 4;
        const int cB = 2 * t + gB;
        u32 B[NF][2];
#pragma unroll
        for (int j = 0; j < NF; j++) {
            int rB = (2 * j + nw) * 8 + rBl;
            u32 swB = ((u32)(((cB ^ rB) & 7) | (cB & 8))) << 4;
            ldm2(B[j], bw + (u32)rB * 256 + swB);
        }
        u32 A[4];
        ldm4(A, ah + oA + swA);
#pragma unroll
        for (int j = 0; j < NF; j++) mma_h(C[j], A, B[j]);
        ldm4(A, al + oA + swA);
#pragma unroll
        for (int j = 0; j < NF; j++) mma_h(C[j], A, B[j]);
    }
}

// ======================= prep kernel: fp32 weights -> swizzled fp16 =======================
extern "C" __global__ void __launch_bounds__(256)
prep_kernel(const float* __restrict__ W1, const float* __restrict__ W2,
            const float* __restrict__ W3, const float* __restrict__ Wc1,
            const float* __restrict__ Ws1)
{
    int idx = blockIdx.x * 256 + threadIdx.x;
    if (idx < 81920) {
        int agent = idx / 10240;
        int rem = idx % 10240;
        int row = rem >> 5;
        int k = (rem & 31) * 4;
        const float* src; int n, N; u32 loff;
        if (row < 128)      { src = W1 + agent * 16384; n = row;       N = 128; loff = 0; }
        else if (row < 256) { src = W2 + agent * 16384; n = row - 128; N = 128; loff = 32768; }
        else                { src = W3 + agent * 8192;  n = row - 256; N = 64;  loff = 65536; }
        u32 h0 = pack_h(src[(k + 0) * N + n], src[(k + 1) * N + n]);
        u32 h1 = pack_h(src[(k + 2) * N + n], src[(k + 3) * N + n]);
        *(uint2*)(g_w + (u32)agent * 81920 + loff + plane_off(n, k)) = make_uint2(h0, h1);
    } else if (idx < 81920 + 1536) {
        int rem = idx - 81920;
        int row = rem >> 5;
        int k = (rem & 31) * 4;
        float w[4];
#pragma unroll
        for (int i = 0; i < 4; i++) {
            int kk = k + i;
            w[i] = (row < 32) ? __ldg(Wc1 + kk * 32 + row) : (row == 32 ? __ldg(Ws1 + kk) : 0.f);
        }
        *(uint2*)(g_ax + plane_off(row, k)) =
            make_uint2(pack_h(w[0], w[1]), pack_h(w[2], w[3]));
    }
}

// ======================= main kernel =======================
extern "C" __global__ void __launch_bounds__(256, 2)
qatten_mma(const float* __restrict__ states,
           const float* __restrict__ b1, const float* __restrict__ b2,
           const float* __restrict__ b3,
           const float* __restrict__ bs1, const float* __restrict__ Ws2,
           const float* __restrict__ bs2,
           const float* __restrict__ bc1, const float* __restrict__ Wc2,
           const float* __restrict__ bc2,
           float* __restrict__ out)
{
    extern __shared__ char smem[];
    const u32 sb = smem_u32(smem);
    const int tid = threadIdx.x;
    const int wid = tid >> 5, lane = tid & 31;
    const int b0 = blockIdx.x * BM;

    const int mq = wid >> 1, nw = wid & 1;
    const int m0 = mq * 16;
    const int q = (lane & 3) * 2;
    const int r0 = m0 + (lane >> 2), r8 = r0 + 8;

    float* sG  = (float*)(smem + SGOFF);
    float* sRd = (float*)(smem + SREDO);

    // ---- prologue: stage states(0); W1(0) + aux -> RW ----
    {
        const unsigned char* S0 = (const unsigned char*)(states + (size_t)b0 * 128);
        for (int i = tid * 16; i < 32768; i += 4096) cp16(sb + RB_HI + i, S0 + i);
        cp_commit();                                        // [S]
        for (int i = tid * 16; i < 32768; i += 4096) cp16(sb + RW + i, g_w + i);
        for (int i = tid * 16; i < 12288; i += 4096) cp16(sb + RW + 32768 + i, g_ax + i);
        cp_commit();                                        // [S, W1]
    }

    float oacc[4][4];
#pragma unroll
    for (int j = 0; j < 4; j++)
#pragma unroll
        for (int i = 0; i < 4; i++) oacc[j][i] = 0.f;
    float creg0 = 0.f, creg1 = 0.f;
    const float r_bs1 = __ldg(bs1), r_Ws2 = __ldg(Ws2), r_bs2 = __ldg(bs2), r_bc2 = __ldg(bc2);

    for (int n = 0; n < NAGENT; n++) {
        // ---- convert staged f32 states -> RA fp16 hi/lo planes ----
        cp_wait<1>();               // states ready (weight group may be pending)
        __syncthreads();            // prev agent's L3 done with RA
#pragma unroll
        for (int i = 0; i < 8; i++) {
            int idx = tid + 256 * i;
            int m = idx >> 5, c4 = idx & 31;
            float4 v;
            asm volatile("ld.shared.v4.f32 {%0,%1,%2,%3}, [%4];"
                : "=f"(v.x), "=f"(v.y), "=f"(v.z), "=f"(v.w)
                : "r"(sb + RB_HI + m * 512 + c4 * 16));
            u32 h0; u32 l0 = split_h(v.x, v.y, h0);
            u32 h1; u32 l1 = split_h(v.z, v.w, h1);
            u32 off = plane_off(m, c4 * 4);
            asm volatile("st.shared.v2.b32 [%0], {%1,%2};" :: "r"(sb + RA_HI + off), "r"(h0), "r"(h1));
            asm volatile("st.shared.v2.b32 [%0], {%1,%2};" :: "r"(sb + RA_LO + off), "r"(l0), "r"(l1));
        }
        cp_wait<0>();               // W1 ready
        __syncthreads();

        // ---- L1 + aux: RA @ [W1 ; Wc1^T ; Ws1]  (N=176) ----
        {
            float C[11][4];
            gemm2<11>(C, sb + RA_HI, sb + RA_LO, sb + RW, m0, nw, lane);
            __syncthreads();        // RW consumed; RB staging consumed (converted)
            {   // stream W2 while epilogue runs
                const unsigned char* src = g_w + (size_t)n * 81920 + 32768;
                for (int i = tid * 16; i < 32768; i += 4096) cp16(sb + RW + i, src + i);
                cp_commit();
            }
            const float* b1n = b1 + n * 128;
            float cp0 = 0.f, cp1 = 0.f;
#pragma unroll
            for (int j = 0; j < 11; j++) {
                int tile = 2 * j + nw;
                if (tile < 16) {            // h1 -> RB planes
                    int col = tile * 8 + q;
                    float bx = __ldg(b1n + col), by = __ldg(b1n + col + 1);
                    float x0 = fmaxf(C[j][0] + bx, 0.f), x1 = fmaxf(C[j][1] + by, 0.f);
                    float x2 = fmaxf(C[j][2] + bx, 0.f), x3 = fmaxf(C[j][3] + by, 0.f);
                    u32 h0; u32 l0 = split_h(x0, x1, h0);
                    u32 h2; u32 l2 = split_h(x2, x3, h2);
                    u32 sw0 = ((u32)(((tile ^ r0) & 7) | (tile & 8))) << 4;
                    u32 sw8 = ((u32)(((tile ^ r8) & 7) | (tile & 8))) << 4;
                    u32 o0 = (u32)r0 * 256 + sw0 + (u32)(q * 2);
                    u32 o8 = (u32)r8 * 256 + sw8 + (u32)(q * 2);
                    asm volatile("st.shared.b32 [%0], %1;" :: "r"(sb + RB_HI + o0), "r"(h0));
                    asm volatile("st.shared.b32 [%0], %1;" :: "r"(sb + RB_LO + o0), "r"(l0));
                    asm volatile("st.shared.b32 [%0], %1;" :: "r"(sb + RB_HI + o8), "r"(h2));
                    asm volatile("st.shared.b32 [%0], %1;" :: "r"(sb + RB_LO + o8), "r"(l2));
                } else if (tile < 20) {     // constraint: e = col-128 in [0,32)
                    int e = (tile - 16) * 8 + q;
                    float bb0 = __ldg(bc1 + e),  bb1 = __ldg(bc1 + e + 1);
                    float w0  = __ldg(Wc2 + e),  w1  = __ldg(Wc2 + e + 1);
                    cp0 = fmaf(fmaxf(C[j][0] + bb0, 0.f), w0, cp0);
                    cp0 = fmaf(fmaxf(C[j][1] + bb1, 0.f), w1, cp0);
                    cp1 = fmaf(fmaxf(C[j][2] + bb0, 0.f), w0, cp1);
                    cp1 = fmaf(fmaxf(C[j][3] + bb1, 0.f), w1, cp1);
                } else if (tile == 20) {    // gate col (e==32) lives at q==0
                    if (q == 0) {
                        float s0 = fmaf(fmaxf(C[j][0] + r_bs1, 0.f), r_Ws2, r_bs2);
                        float s8 = fmaf(fmaxf(C[j][2] + r_bs1, 0.f), r_Ws2, r_bs2);
                        sG[r0] = 1.f / (1.f + __expf(-s0));
                        sG[r8] = 1.f / (1.f + __expf(-s8));
                    }
                }
            }
            cp0 += __shfl_xor_sync(0xffffffffu, cp0, 1);
            cp0 += __shfl_xor_sync(0xffffffffu, cp0, 2);
            cp1 += __shfl_xor_sync(0xffffffffu, cp1, 1);
            cp1 += __shfl_xor_sync(0xffffffffu, cp1, 2);
            if ((lane & 3) == 0) {
                creg0 += cp0 + (nw == 0 ? r_bc2 : 0.f);
                creg1 += cp1 + (nw == 0 ? r_bc2 : 0.f);
            }
        }
        cp_wait<0>();
        __syncthreads();

        // ---- L2: RB @ W2 -> RA planes ----
        {
            float C[8][4];
            gemm2<8>(C, sb + RB_HI, sb + RB_LO, sb + RW, m0, nw, lane);
            __syncthreads();        // RW, RB consumed
            {   // stream W3 + states(n+1)
                const unsigned char* src = g_w + (size_t)n * 81920 + 65536;
                for (int i = tid * 16; i < 16384; i += 4096) cp16(sb + RW + i, src + i);
                cp_commit();        // [W3]
                if (n < NAGENT - 1) {
                    const unsigned char* Sn =
                        (const unsigned char*)(states + ((size_t)(n + 1) * BATCH + b0) * 128);
                    for (int i = tid * 16; i < 32768; i += 4096) cp16(sb + RB_HI + i, Sn + i);
                }
                cp_commit();        // [W3, S']
            }
            const float* b2n = b2 + n * 128;
#pragma unroll
            for (int j = 0; j < 8; j++) {
                int tile = 2 * j + nw;
                int col = tile * 8 + q;
                float bx = __ldg(b2n + col), by = __ldg(b2n + col + 1);
                float x0 = fmaxf(C[j][0] + bx, 0.f), x1 = fmaxf(C[j][1] + by, 0.f);
                float x2 = fmaxf(C[j][2] + bx, 0.f), x3 = fmaxf(C[j][3] + by, 0.f);
                u32 h0; u32 l0 = split_h(x0, x1, h0);
                u32 h2; u32 l2 = split_h(x2, x3, h2);
                u32 sw0 = ((u32)(((tile ^ r0) & 7) | (tile & 8))) << 4;
                u32 sw8 = ((u32)(((tile ^ r8) & 7) | (tile & 8))) << 4;
                u32 o0 = (u32)r0 * 256 + sw0 + (u32)(q * 2);
                u32 o8 = (u32)r8 * 256 + sw8 + (u32)(q * 2);
                asm volatile("st.shared.b32 [%0], %1;" :: "r"(sb + RA_HI + o0), "r"(h0));
                asm volatile("st.shared.b32 [%0], %1;" :: "r"(sb + RA_LO + o0), "r"(l0));
                asm volatile("st.shared.b32 [%0], %1;" :: "r"(sb + RA_HI + o8), "r"(h2));
                asm volatile("st.shared.b32 [%0], %1;" :: "r"(sb + RA_LO + o8), "r"(l2));
            }
        }
        cp_wait<1>();               // W3 ready (states still streaming)
        __syncthreads();

        // ---- L3: RA @ W3 (N=64) -> oacc ----
        {
            float C[4][4];
            gemm2<4>(C, sb + RA_HI, sb + RA_LO, sb + RW, m0, nw, lane);
            __syncthreads();        // RA, RW consumed
            if (n < NAGENT - 1) {   // stream W1(n+1)  (aux rows persist)
                const unsigned char* src = g_w + (size_t)(n + 1) * 81920;
                for (int i = tid * 16; i < 32768; i += 4096) cp16(sb + RW + i, src + i);
            }
            cp_commit();            // [S', W1']
            const float* b3n = b3 + n * 64;
            float g0 = sG[r0], g8 = sG[r8];
#pragma unroll
            for (int j = 0; j < 4; j++) {
                int col = (2 * j + nw) * 8 + q;
                float bx = __ldg(b3n + col), by = __ldg(b3n + col + 1);
                oacc[j][0] = fmaf(g0, C[j][0] + bx, oacc[j][0]);
                oacc[j][1] = fmaf(g0, C[j][1] + by, oacc[j][1]);
                oacc[j][2] = fmaf(g8, C[j][2] + bx, oacc[j][2]);
                oacc[j][3] = fmaf(g8, C[j][3] + by, oacc[j][3]);
            }
        }
    }

    // ---- final: csum exchange + output ----
    if ((lane & 3) == 0) {
        sRd[r0 * 2 + nw] = creg0;
        sRd[r8 * 2 + nw] = creg1;
    }
    __syncthreads();
    {
        float cs0 = (sRd[r0 * 2] + sRd[r0 * 2 + 1]) * 0.125f;
        float cs8 = (sRd[r8 * 2] + sRd[r8 * 2 + 1]) * 0.125f;
#pragma unroll
        for (int j = 0; j < 4; j++) {
            int col = (2 * j + nw) * 8 + q;
            float2 v0, v8;
            v0.x = fmaf(oacc[j][0], 0.125f, cs0);
            v0.y = fmaf(oacc[j][1], 0.125f, cs0);
            v8.x = fmaf(oacc[j][2], 0.125f, cs8);
            v8.y = fmaf(oacc[j][3], 0.125f, cs8);
            *(float2*)(out + (size_t)(b0 + r0) * 64 + col) = v0;
            *(float2*)(out + (size_t)(b0 + r8) * 64 + col) = v8;
        }
    }
}

extern "C" void kernel_launch(void* const* d_in, const int* in_sizes, int n_in,
                              void* d_out, int out_size)
{
    const float* states = (const float*)d_in[0];
    const float* W1  = (const float*)d_in[1];
    const float* b1  = (const float*)d_in[2];
    const float* W2  = (const float*)d_in[3];
    const float* b2  = (const float*)d_in[4];
    const float* W3  = (const float*)d_in[5];
    const float* b3  = (const float*)d_in[6];
    // d_in[7..12]: Wq1,bq1,Wq2,bq2,Wk,bk — dead (softmax rows sum to 1)
    const float* Ws1 = (const float*)d_in[13];
    const float* bs1 = (const float*)d_in[14];
    const float* Ws2 = (const float*)d_in[15];
    const float* bs2 = (const float*)d_in[16];
    const float* Wc1 = (const float*)d_in[17];
    const float* bc1 = (const float*)d_in[18];
    const float* Wc2 = (const float*)d_in[19];
    const float* bc2 = (const float*)d_in[20];
    float* out = (float*)d_out;

    prep_kernel<<<(81920 + 1536 + 255) / 256, 256>>>(W1, W2, W3, Wc1, Ws1);

    cudaFuncSetAttribute(qatten_mma,
                         cudaFuncAttributeMaxDynamicSharedMemorySize, SMEM_TOTAL);
    qatten_mma<<<BATCH / BM, 256, SMEM_TOTAL>>>(
        states, b1, b2, b3, bs1, Ws2, bs2, bc1, Wc2, bc2, out);
}

// round 7
// speedup vs baseline: 6.0048x; 1.5892x over previous
#include <cuda_runtime.h>
#include <cuda_fp16.h>
#include <cstdint>

typedef unsigned u32;

#define NAGENT 8
#define BATCH  32768
#define BM     64

// ---- scratch: pre-swizzled fp16 weights ----
// per agent: L1 (128 rows) off 0, L2 off 32768, L3 (64 rows) off 65536; stride 81920
__device__ __align__(16) unsigned char g_w[8 * 81920];
__device__ __align__(16) unsigned char g_ax[48 * 256];   // aux: Wc1^T rows 0-31, Ws1 row 32, pad

// ---- smem byte offsets (per CTA, ~109 KB -> 2 CTAs/SM) ----
#define RA    0          // 64 rows x 256B fp16 plane (activations in)
#define RB    16384      // 64 rows x 256B fp16 plane (activations out)
#define RST   32768      // f32 states staging (64 x 512B = 32KB)
#define RW    65536      // weights, 176 rows x 256B = 45056 (aux rows 128-175 persist)
#define SGOFF 110592     // gate per row (64 f32)
#define SREDO 110848     // csum partials (64 rows x 2 warps)
#define SMEM_TOTAL 111616

// ======================= helpers =======================
__device__ __forceinline__ u32 smem_u32(const void* p) {
    u32 a; asm("{ .reg .u64 t; cvta.to.shared.u64 t, %1; cvt.u32.u64 %0, t; }" : "=r"(a) : "l"(p));
    return a;
}
__device__ __forceinline__ void cp16(u32 dst, const void* src) {
    asm volatile("cp.async.cg.shared.global [%0], [%1], 16;" :: "r"(dst), "l"(src));
}
__device__ __forceinline__ void cp_commit() { asm volatile("cp.async.commit_group;"); }
template<int N> __device__ __forceinline__ void cp_wait() {
    asm volatile("cp.async.wait_group %0;" :: "n"(N) : "memory");
}
__device__ __forceinline__ u32 pack_h(float x, float y) {
    __half2 h = __floats2half2_rn(x, y);
    return *reinterpret_cast<u32*>(&h);
}
// plane byte offset: row n, half-col k; 256B rows, XOR swizzle on 16B chunks
__device__ __forceinline__ u32 plane_off(int n, int k) {
    int c = k >> 3;
    u32 sw = (u32)(((c ^ n) & 7) | (c & 8));
    return (u32)(n * 256) + (sw << 4) + (u32)((k & 7) * 2);
}
__device__ __forceinline__ void ldm4(u32* a, u32 addr) {
    asm volatile("ldmatrix.sync.aligned.m8n8.x4.shared.b16 {%0,%1,%2,%3}, [%4];"
        : "=r"(a[0]), "=r"(a[1]), "=r"(a[2]), "=r"(a[3]) : "r"(addr));
}
__device__ __forceinline__ void ldm2(u32* b, u32 addr) {
    asm volatile("ldmatrix.sync.aligned.m8n8.x2.shared.b16 {%0,%1}, [%2];"
        : "=r"(b[0]), "=r"(b[1]) : "r"(addr));
}
__device__ __forceinline__ void mma_h(float* d, const u32* a, const u32* b) {
    asm volatile("mma.sync.aligned.m16n8k16.row.col.f32.f16.f16.f32 "
        "{%0,%1,%2,%3}, {%4,%5,%6,%7}, {%8,%9}, {%0,%1,%2,%3};"
        : "+f"(d[0]), "+f"(d[1]), "+f"(d[2]), "+f"(d[3])
        : "r"(a[0]), "r"(a[1]), "r"(a[2]), "r"(a[3]), "r"(b[0]), "r"(b[1]));
}

// ======================= warp GEMM (single-pass fp16, paired x4 B loads) ===========
// C[NF][4] = A[16 rows @ m0, K=128] @ W[tiles (2j+nw)]^T
template<int NF>
__device__ __forceinline__ void gemm1(float C[NF][4], u32 ah, u32 bw,
                                      int m0, int nw, int lane)
{
#pragma unroll
    for (int j = 0; j < NF; j++)
#pragma unroll
        for (int i = 0; i < 4; i++) C[j][i] = 0.f;

    const int rA = m0 + (lane & 7) + ((lane >> 3) & 1) * 8;
    const int gA = lane >> 4;
    const u32 oA = (u32)rA * 256;
    const int rBl = lane & 7;
    const int gB = (lane >> 3) & 1;
    const int tsel = (lane >> 4) & 1;   // which tile of the x4-pair this lane addresses

#pragma unroll
    for (int t = 0; t < 8; t++) {
        const int cA = 2 * t + gA;
        const u32 swA = ((u32)(((cA ^ rA) & 7) | (cA & 8))) << 4;
        u32 A[4];
        ldm4(A, ah + oA + swA);

        const int cB = 2 * t + gB;
#pragma unroll
        for (int jp = 0; jp < NF / 2; jp++) {
            int tile = 4 * jp + nw + 2 * tsel;       // lanes 0-15: pair lo, 16-31: pair hi
            int rB = tile * 8 + rBl;
            u32 swB = ((u32)(((cB ^ rB) & 7) | (cB & 8))) << 4;
            u32 B4[4];
            ldm4(B4, bw + (u32)rB * 256 + swB);      // b0,b1 = tile lo; b2,b3 = tile hi
            mma_h(C[2 * jp],     A, B4);
            mma_h(C[2 * jp + 1], A, B4 + 2);
        }
        if (NF & 1) {
            int tile = 2 * (NF - 1) + nw;
            int rB = tile * 8 + rBl;
            u32 swB = ((u32)(((cB ^ rB) & 7) | (cB & 8))) << 4;
            u32 B2[2];
            ldm2(B2, bw + (u32)rB * 256 + swB);
            mma_h(C[NF - 1], A, B2);
        }
    }
}

// ======================= prep kernel: fp32 weights -> swizzled fp16 =======================
extern "C" __global__ void __launch_bounds__(256)
prep_kernel(const float* __restrict__ W1, const float* __restrict__ W2,
            const float* __restrict__ W3, const float* __restrict__ Wc1,
            const float* __restrict__ Ws1)
{
    int idx = blockIdx.x * 256 + threadIdx.x;
    if (idx < 81920) {
        int agent = idx / 10240;
        int rem = idx % 10240;
        int row = rem >> 5;
        int k = (rem & 31) * 4;
        const float* src; int n, N; u32 loff;
        if (row < 128)      { src = W1 + agent * 16384; n = row;       N = 128; loff = 0; }
        else if (row < 256) { src = W2 + agent * 16384; n = row - 128; N = 128; loff = 32768; }
        else                { src = W3 + agent * 8192;  n = row - 256; N = 64;  loff = 65536; }
        u32 h0 = pack_h(src[(k + 0) * N + n], src[(k + 1) * N + n]);
        u32 h1 = pack_h(src[(k + 2) * N + n], src[(k + 3) * N + n]);
        *(uint2*)(g_w + (u32)agent * 81920 + loff + plane_off(n, k)) = make_uint2(h0, h1);
    } else if (idx < 81920 + 1536) {
        int rem = idx - 81920;
        int row = rem >> 5;
        int k = (rem & 31) * 4;
        float w[4];
#pragma unroll
        for (int i = 0; i < 4; i++) {
            int kk = k + i;
            w[i] = (row < 32) ? __ldg(Wc1 + kk * 32 + row) : (row == 32 ? __ldg(Ws1 + kk) : 0.f);
        }
        *(uint2*)(g_ax + plane_off(row, k)) =
            make_uint2(pack_h(w[0], w[1]), pack_h(w[2], w[3]));
    }
}

// ======================= main kernel =======================
extern "C" __global__ void __launch_bounds__(256, 2)
qatten_mma(const float* __restrict__ states,
           const float* __restrict__ b1, const float* __restrict__ b2,
           const float* __restrict__ b3,
           const float* __restrict__ bs1, const float* __restrict__ Ws2,
           const float* __restrict__ bs2,
           const float* __restrict__ bc1, const float* __restrict__ Wc2,
           const float* __restrict__ bc2,
           float* __restrict__ out)
{
    extern __shared__ char smem[];
    const u32 sb = smem_u32(smem);
    const int tid = threadIdx.x;
    const int wid = tid >> 5, lane = tid & 31;
    const int b0 = blockIdx.x * BM;

    const int mq = wid >> 1, nw = wid & 1;
    const int m0 = mq * 16;
    const int q = (lane & 3) * 2;
    const int r0 = m0 + (lane >> 2), r8 = r0 + 8;

    float* sG  = (float*)(smem + SGOFF);
    float* sRd = (float*)(smem + SREDO);

    // ---- prologue: stage states(0) -> RST; W1(0) + aux -> RW ----
    {
        const unsigned char* S0 = (const unsigned char*)(states + (size_t)b0 * 128);
        for (int i = tid * 16; i < 32768; i += 4096) cp16(sb + RST + i, S0 + i);
        cp_commit();                                        // [S]
        for (int i = tid * 16; i < 32768; i += 4096) cp16(sb + RW + i, g_w + i);
        for (int i = tid * 16; i < 12288; i += 4096) cp16(sb + RW + 32768 + i, g_ax + i);
        cp_commit();                                        // [S, W1]
    }

    float oacc[4][4];
#pragma unroll
    for (int j = 0; j < 4; j++)
#pragma unroll
        for (int i = 0; i < 4; i++) oacc[j][i] = 0.f;
    float creg0 = 0.f, creg1 = 0.f;
    const float r_bs1 = __ldg(bs1), r_Ws2 = __ldg(Ws2), r_bs2 = __ldg(bs2), r_bc2 = __ldg(bc2);

    for (int n = 0; n < NAGENT; n++) {
        // ---- convert staged f32 states -> RA fp16 plane ----
        cp_wait<1>();               // states ready (weight group may be pending)
        __syncthreads();            // prev agent's L3 done with RA
#pragma unroll
        for (int i = 0; i < 8; i++) {
            int idx = tid + 256 * i;
            int m = idx >> 5, c4 = idx & 31;
            float4 v;
            asm volatile("ld.shared.v4.f32 {%0,%1,%2,%3}, [%4];"
                : "=f"(v.x), "=f"(v.y), "=f"(v.z), "=f"(v.w)
                : "r"(sb + RST + m * 512 + c4 * 16));
            u32 h0 = pack_h(v.x, v.y);
            u32 h1 = pack_h(v.z, v.w);
            asm volatile("st.shared.v2.b32 [%0], {%1,%2};"
                :: "r"(sb + RA + plane_off(m, c4 * 4)), "r"(h0), "r"(h1));
        }
        cp_wait<0>();               // W1 ready
        __syncthreads();

        // ---- L1 + aux: RA @ [W1 ; Wc1^T ; Ws1]  (N=176) ----
        {
            float C[11][4];
            gemm1<11>(C, sb + RA, sb + RW, m0, nw, lane);
            __syncthreads();        // RW consumed; RST consumed (converted)
            {   // stream W2 while epilogue runs
                const unsigned char* src = g_w + (size_t)n * 81920 + 32768;
                for (int i = tid * 16; i < 32768; i += 4096) cp16(sb + RW + i, src + i);
                cp_commit();
            }
            const float* b1n = b1 + n * 128;
            float cp0 = 0.f, cp1 = 0.f;
#pragma unroll
            for (int j = 0; j < 11; j++) {
                int tile = 2 * j + nw;
                if (tile < 16) {            // h1 -> RB plane
                    int col = tile * 8 + q;
                    float bx = __ldg(b1n + col), by = __ldg(b1n + col + 1);
                    u32 h0 = pack_h(fmaxf(C[j][0] + bx, 0.f), fmaxf(C[j][1] + by, 0.f));
                    u32 h2 = pack_h(fmaxf(C[j][2] + bx, 0.f), fmaxf(C[j][3] + by, 0.f));
                    u32 sw0 = ((u32)(((tile ^ r0) & 7) | (tile & 8))) << 4;
                    u32 sw8 = ((u32)(((tile ^ r8) & 7) | (tile & 8))) << 4;
                    asm volatile("st.shared.b32 [%0], %1;"
                        :: "r"(sb + RB + (u32)r0 * 256 + sw0 + (u32)(q * 2)), "r"(h0));
                    asm volatile("st.shared.b32 [%0], %1;"
                        :: "r"(sb + RB + (u32)r8 * 256 + sw8 + (u32)(q * 2)), "r"(h2));
                } else if (tile < 20) {     // constraint: e = col-128 in [0,32)
                    int e = (tile - 16) * 8 + q;
                    float bb0 = __ldg(bc1 + e),  bb1 = __ldg(bc1 + e + 1);
                    float w0  = __ldg(Wc2 + e),  w1  = __ldg(Wc2 + e + 1);
                    cp0 = fmaf(fmaxf(C[j][0] + bb0, 0.f), w0, cp0);
                    cp0 = fmaf(fmaxf(C[j][1] + bb1, 0.f), w1, cp0);
                    cp1 = fmaf(fmaxf(C[j][2] + bb0, 0.f), w0, cp1);
                    cp1 = fmaf(fmaxf(C[j][3] + bb1, 0.f), w1, cp1);
                } else if (tile == 20) {    // gate col (e==32) lives at q==0
                    if (q == 0) {
                        float s0 = fmaf(fmaxf(C[j][0] + r_bs1, 0.f), r_Ws2, r_bs2);
                        float s8 = fmaf(fmaxf(C[j][2] + r_bs1, 0.f), r_Ws2, r_bs2);
                        sG[r0] = 1.f / (1.f + __expf(-s0));
                        sG[r8] = 1.f / (1.f + __expf(-s8));
                    }
                }
            }
            cp0 += __shfl_xor_sync(0xffffffffu, cp0, 1);
            cp0 += __shfl_xor_sync(0xffffffffu, cp0, 2);
            cp1 += __shfl_xor_sync(0xffffffffu, cp1, 1);
            cp1 += __shfl_xor_sync(0xffffffffu, cp1, 2);
            if ((lane & 3) == 0) {
                creg0 += cp0 + (nw == 0 ? r_bc2 : 0.f);
                creg1 += cp1 + (nw == 0 ? r_bc2 : 0.f);
            }
        }
        cp_wait<0>();
        __syncthreads();

        // ---- L2: RB @ W2 -> RA plane ----
        {
            float C[8][4];
            gemm1<8>(C, sb + RB, sb + RW, m0, nw, lane);
            __syncthreads();        // RW, RB consumed
            {   // stream W3 + states(n+1)
                const unsigned char* src = g_w + (size_t)n * 81920 + 65536;
                for (int i = tid * 16; i < 16384; i += 4096) cp16(sb + RW + i, src + i);
                cp_commit();        // [W3]
                if (n < NAGENT - 1) {
                    const unsigned char* Sn =
                        (const unsigned char*)(states + ((size_t)(n + 1) * BATCH + b0) * 128);
                    for (int i = tid * 16; i < 32768; i += 4096) cp16(sb + RST + i, Sn + i);
                }
                cp_commit();        // [W3, S']
            }
            const float* b2n = b2 + n * 128;
#pragma unroll
            for (int j = 0; j < 8; j++) {
                int tile = 2 * j + nw;
                int col = tile * 8 + q;
                float bx = __ldg(b2n + col), by = __ldg(b2n + col + 1);
                u32 h0 = pack_h(fmaxf(C[j][0] + bx, 0.f), fmaxf(C[j][1] + by, 0.f));
                u32 h2 = pack_h(fmaxf(C[j][2] + bx, 0.f), fmaxf(C[j][3] + by, 0.f));
                u32 sw0 = ((u32)(((tile ^ r0) & 7) | (tile & 8))) << 4;
                u32 sw8 = ((u32)(((tile ^ r8) & 7) | (tile & 8))) << 4;
                asm volatile("st.shared.b32 [%0], %1;"
                    :: "r"(sb + RA + (u32)r0 * 256 + sw0 + (u32)(q * 2)), "r"(h0));
                asm volatile("st.shared.b32 [%0], %1;"
                    :: "r"(sb + RA + (u32)r8 * 256 + sw8 + (u32)(q * 2)), "r"(h2));
            }
        }
        cp_wait<1>();               // W3 ready (states still streaming)
        __syncthreads();

        // ---- L3: RA @ W3 (N=64) -> oacc ----
        {
            float C[4][4];
            gemm1<4>(C, sb + RA, sb + RW, m0, nw, lane);
            __syncthreads();        // RA, RW consumed
            if (n < NAGENT - 1) {   // stream W1(n+1)  (aux rows persist)
                const unsigned char* src = g_w + (size_t)(n + 1) * 81920;
                for (int i = tid * 16; i < 32768; i += 4096) cp16(sb + RW + i, src + i);
            }
            cp_commit();            // [S', W1']
            const float* b3n = b3 + n * 64;
            float g0 = sG[r0], g8 = sG[r8];
#pragma unroll
            for (int j = 0; j < 4; j++) {
                int col = (2 * j + nw) * 8 + q;
                float bx = __ldg(b3n + col), by = __ldg(b3n + col + 1);
                oacc[j][0] = fmaf(g0, C[j][0] + bx, oacc[j][0]);
                oacc[j][1] = fmaf(g0, C[j][1] + by, oacc[j][1]);
                oacc[j][2] = fmaf(g8, C[j][2] + bx, oacc[j][2]);
                oacc[j][3] = fmaf(g8, C[j][3] + by, oacc[j][3]);
            }
        }
    }

    // ---- final: csum exchange + output ----
    if ((lane & 3) == 0) {
        sRd[r0 * 2 + nw] = creg0;
        sRd[r8 * 2 + nw] = creg1;
    }
    __syncthreads();
    {
        float cs0 = (sRd[r0 * 2] + sRd[r0 * 2 + 1]) * 0.125f;
        float cs8 = (sRd[r8 * 2] + sRd[r8 * 2 + 1]) * 0.125f;
#pragma unroll
        for (int j = 0; j < 4; j++) {
            int col = (2 * j + nw) * 8 + q;
            float2 v0, v8;
            v0.x = fmaf(oacc[j][0], 0.125f, cs0);
            v0.y = fmaf(oacc[j][1], 0.125f, cs0);
            v8.x = fmaf(oacc[j][2], 0.125f, cs8);
            v8.y = fmaf(oacc[j][3], 0.125f, cs8);
            *(float2*)(out + (size_t)(b0 + r0) * 64 + col) = v0;
            *(float2*)(out + (size_t)(b0 + r8) * 64 + col) = v8;
        }
    }
}

extern "C" void kernel_launch(void* const* d_in, const int* in_sizes, int n_in,
                              void* d_out, int out_size)
{
    const float* states = (const float*)d_in[0];
    const float* W1  = (const float*)d_in[1];
    const float* b1  = (const float*)d_in[2];
    const float* W2  = (const float*)d_in[3];
    const float* b2  = (const float*)d_in[4];
    const float* W3  = (const float*)d_in[5];
    const float* b3  = (const float*)d_in[6];
    // d_in[7..12]: Wq1,bq1,Wq2,bq2,Wk,bk — dead (softmax rows sum to 1)
    const float* Ws1 = (const float*)d_in[13];
    const float* bs1 = (const float*)d_in[14];
    const float* Ws2 = (const float*)d_in[15];
    const float* bs2 = (const float*)d_in[16];
    const float* Wc1 = (const float*)d_in[17];
    const float* bc1 = (const float*)d_in[18];
    const float* Wc2 = (const float*)d_in[19];
    const float* bc2 = (const float*)d_in[20];
    float* out = (float*)d_out;

    prep_kernel<<<(81920 + 1536 + 255) / 256, 256>>>(W1, W2, W3, Wc1, Ws1);

    cudaFuncSetAttribute(qatten_mma,
                         cudaFuncAttributeMaxDynamicSharedMemorySize, SMEM_TOTAL);
    qatten_mma<<<BATCH / BM, 256, SMEM_TOTAL>>>(
        states, b1, b2, b3, bs1, Ws2, bs2, bc1, Wc2, bc2, out);
}

// round 8
// speedup vs baseline: 6.6968x; 1.1152x over previous
#include <cuda_runtime.h>
#include <cuda_fp16.h>
#include <cstdint>

typedef unsigned u32;

#define NAGENT 8
#define BATCH  32768
#define BM     64

// ---- scratch: pre-swizzled fp16 weights ----
// per agent: L1 (128 rows) off 0, L2 off 32768, L3 (64 rows) off 65536; stride 81920
__device__ __align__(16) unsigned char g_w[8 * 81920];
__device__ __align__(16) unsigned char g_ax[48 * 256];   // aux: Wc1^T rows 0-31, Ws1 row 32, pad

// ---- smem byte offsets (per CTA, ~109 KB -> 2 CTAs/SM) ----
#define RA    0          // 64 rows x 256B fp16 plane (activations in)
#define RB    16384      // 64 rows x 256B fp16 plane (activations out)
#define RST   32768      // f32 states staging (64 x 512B = 32KB)
#define RW    65536      // weights, 176 rows x 256B = 45056 (aux rows 128-175 persist)
#define SGOFF 110592     // gate per row (64 f32)
#define SREDO 110848     // csum partials (64 rows x 2 slots)
#define SMEM_TOTAL 111616

// ======================= helpers =======================
__device__ __forceinline__ u32 smem_u32(const void* p) {
    u32 a; asm("{ .reg .u64 t; cvta.to.shared.u64 t, %1; cvt.u32.u64 %0, t; }" : "=r"(a) : "l"(p));
    return a;
}
__device__ __forceinline__ void cp16(u32 dst, const void* src) {
    asm volatile("cp.async.cg.shared.global [%0], [%1], 16;" :: "r"(dst), "l"(src));
}
__device__ __forceinline__ void cp_commit() { asm volatile("cp.async.commit_group;"); }
template<int N> __device__ __forceinline__ void cp_wait() {
    asm volatile("cp.async.wait_group %0;" :: "n"(N) : "memory");
}
__device__ __forceinline__ u32 pack_h(float x, float y) {
    __half2 h = __floats2half2_rn(x, y);
    return *reinterpret_cast<u32*>(&h);
}
// plane byte offset: row n, half-col k; 256B rows, XOR swizzle on 16B chunks
__device__ __forceinline__ u32 plane_off(int n, int k) {
    int c = k >> 3;
    u32 sw = (u32)(((c ^ n) & 7) | (c & 8));
    return (u32)(n * 256) + (sw << 4) + (u32)((k & 7) * 2);
}
__device__ __forceinline__ void ldm4(u32* a, u32 addr) {
    asm volatile("ldmatrix.sync.aligned.m8n8.x4.shared.b16 {%0,%1,%2,%3}, [%4];"
        : "=r"(a[0]), "=r"(a[1]), "=r"(a[2]), "=r"(a[3]) : "r"(addr));
}
__device__ __forceinline__ void ldm2(u32* b, u32 addr) {
    asm volatile("ldmatrix.sync.aligned.m8n8.x2.shared.b16 {%0,%1}, [%2];"
        : "=r"(b[0]), "=r"(b[1]) : "r"(addr));
}
__device__ __forceinline__ void mma_h(float* d, const u32* a, const u32* b) {
    asm volatile("mma.sync.aligned.m16n8k16.row.col.f32.f16.f16.f32 "
        "{%0,%1,%2,%3}, {%4,%5,%6,%7}, {%8,%9}, {%0,%1,%2,%3};"
        : "+f"(d[0]), "+f"(d[1]), "+f"(d[2]), "+f"(d[3])
        : "r"(a[0]), "r"(a[1]), "r"(a[2]), "r"(a[3]), "r"(b[0]), "r"(b[1]));
}

// ============ warp GEMM: 32 M-rows (MF=2), NF n8-tiles, paired x4 B loads ============
// C[2][NF][4] = A[rows m0..m0+32, K=128] @ W[tiles tbase..tbase+NF]^T
template<int NF>
__device__ __forceinline__ void gemm2m(float C[2][NF][4], u32 ah, u32 bw,
                                       int m0, int tbase, int lane)
{
#pragma unroll
    for (int mf = 0; mf < 2; mf++)
#pragma unroll
        for (int j = 0; j < NF; j++)
#pragma unroll
            for (int i = 0; i < 4; i++) C[mf][j][i] = 0.f;

    const int rA = m0 + (lane & 7) + ((lane >> 3) & 1) * 8;
    const int gA = lane >> 4;
    const u32 oA = (u32)rA * 256;
    const int rBl = lane & 7;
    const int gB = (lane >> 3) & 1;
    const int tsel = (lane >> 4) & 1;

#pragma unroll
    for (int t = 0; t < 8; t++) {
        const int cA = 2 * t + gA;
        const u32 swA = ((u32)(((cA ^ rA) & 7) | (cA & 8))) << 4;
        u32 A0[4], A1[4];
        ldm4(A0, ah + oA + swA);            // rows m0..m0+15
        ldm4(A1, ah + oA + 4096 + swA);     // rows m0+16..m0+31 (same swizzle: row&7 equal)

        const int cB = 2 * t + gB;
#pragma unroll
        for (int jp = 0; jp < NF / 2; jp++) {
            int tile = tbase + 2 * jp + tsel;    // lanes 0-15: pair lo, 16-31: pair hi
            int rB = tile * 8 + rBl;
            u32 swB = ((u32)(((cB ^ rB) & 7) | (cB & 8))) << 4;
            u32 B4[4];
            ldm4(B4, bw + (u32)rB * 256 + swB);  // b0,b1 = tile lo; b2,b3 = tile hi
            mma_h(C[0][2 * jp],     A0, B4);
            mma_h(C[0][2 * jp + 1], A0, B4 + 2);
            mma_h(C[1][2 * jp],     A1, B4);
            mma_h(C[1][2 * jp + 1], A1, B4 + 2);
        }
        if (NF & 1) {
            int tile = tbase + NF - 1;
            int rB = tile * 8 + rBl;
            u32 swB = ((u32)(((cB ^ rB) & 7) | (cB & 8))) << 4;
            u32 B2[2];
            ldm2(B2, bw + (u32)rB * 256 + swB);
            mma_h(C[0][NF - 1], A0, B2);
            mma_h(C[1][NF - 1], A1, B2);
        }
    }
}

// ======================= L1 epilogue (RB stores + aux) =======================
template<int NF, int TBASE>
__device__ __forceinline__ void epi_L1(float C[2][NF][4], u32 sb,
    const float* __restrict__ b1n, const float* __restrict__ bc1,
    const float* __restrict__ Wc2,
    float r_bs1, float r_Ws2, float r_bs2, float r_bc2,
    float* sG, float* sRd, float creg[4], int m0, int lane, int q)
{
    float cp[4] = {0.f, 0.f, 0.f, 0.f};
#pragma unroll
    for (int j = 0; j < NF; j++) {
        constexpr int dummy = 0; (void)dummy;
        const int tile = TBASE + j;
        if (tile < 16) {
            int col = tile * 8 + q;
            float bx = __ldg(b1n + col), by = __ldg(b1n + col + 1);
#pragma unroll
            for (int mf = 0; mf < 2; mf++) {
                int row0 = m0 + mf * 16 + (lane >> 2), row8 = row0 + 8;
                u32 h0 = pack_h(fmaxf(C[mf][j][0] + bx, 0.f), fmaxf(C[mf][j][1] + by, 0.f));
                u32 h2 = pack_h(fmaxf(C[mf][j][2] + bx, 0.f), fmaxf(C[mf][j][3] + by, 0.f));
                u32 sw0 = ((u32)(((tile ^ row0) & 7) | (tile & 8))) << 4;
                u32 sw8 = ((u32)(((tile ^ row8) & 7) | (tile & 8))) << 4;
                asm volatile("st.shared.b32 [%0], %1;"
                    :: "r"(sb + RB + (u32)row0 * 256 + sw0 + (u32)(q * 2)), "r"(h0));
                asm volatile("st.shared.b32 [%0], %1;"
                    :: "r"(sb + RB + (u32)row8 * 256 + sw8 + (u32)(q * 2)), "r"(h2));
            }
        } else if (tile < 20) {     // constraint cols: e in [0,32)
            int e = (tile - 16) * 8 + q;
            float bb0 = __ldg(bc1 + e),  bb1 = __ldg(bc1 + e + 1);
            float w0  = __ldg(Wc2 + e),  w1  = __ldg(Wc2 + e + 1);
#pragma unroll
            for (int mf = 0; mf < 2; mf++) {
                cp[mf * 2 + 0] = fmaf(fmaxf(C[mf][j][0] + bb0, 0.f), w0,
                                 fmaf(fmaxf(C[mf][j][1] + bb1, 0.f), w1, cp[mf * 2 + 0]));
                cp[mf * 2 + 1] = fmaf(fmaxf(C[mf][j][2] + bb0, 0.f), w0,
                                 fmaf(fmaxf(C[mf][j][3] + bb1, 0.f), w1, cp[mf * 2 + 1]));
            }
        } else if (tile == 20) {    // gate col (e==32) at q==0
            if (q == 0) {
#pragma unroll
                for (int mf = 0; mf < 2; mf++) {
                    int row0 = m0 + mf * 16 + (lane >> 2), row8 = row0 + 8;
                    float s0 = fmaf(fmaxf(C[mf][j][0] + r_bs1, 0.f), r_Ws2, r_bs2);
                    float s8 = fmaf(fmaxf(C[mf][j][2] + r_bs1, 0.f), r_Ws2, r_bs2);
                    sG[row0] = 1.f / (1.f + __expf(-s0));
                    sG[row8] = 1.f / (1.f + __expf(-s8));
                }
            }
        }
        // tile 21: zero padding, skip
    }
    if (TBASE >= 12) {              // constraint-carrying warps (nw 2,3)
#pragma unroll
        for (int i = 0; i < 4; i++) {
            cp[i] += __shfl_xor_sync(0xffffffffu, cp[i], 1);
            cp[i] += __shfl_xor_sync(0xffffffffu, cp[i], 2);
        }
        if ((lane & 3) == 0) {
            float add = (TBASE == 12) ? r_bc2 : 0.f;
#pragma unroll
            for (int i = 0; i < 4; i++) creg[i] += cp[i] + add;
        }
    }
    (void)sRd;
}

// ======================= prep kernel: fp32 weights -> swizzled fp16 =======================
extern "C" __global__ void __launch_bounds__(256)
prep_kernel(const float* __restrict__ W1, const float* __restrict__ W2,
            const float* __restrict__ W3, const float* __restrict__ Wc1,
            const float* __restrict__ Ws1)
{
    int idx = blockIdx.x * 256 + threadIdx.x;
    if (idx < 81920) {
        int agent = idx / 10240;
        int rem = idx % 10240;
        int row = rem >> 5;
        int k = (rem & 31) * 4;
        const float* src; int n, N; u32 loff;
        if (row < 128)      { src = W1 + agent * 16384; n = row;       N = 128; loff = 0; }
        else if (row < 256) { src = W2 + agent * 16384; n = row - 128; N = 128; loff = 32768; }
        else                { src = W3 + agent * 8192;  n = row - 256; N = 64;  loff = 65536; }
        u32 h0 = pack_h(src[(k + 0) * N + n], src[(k + 1) * N + n]);
        u32 h1 = pack_h(src[(k + 2) * N + n], src[(k + 3) * N + n]);
        *(uint2*)(g_w + (u32)agent * 81920 + loff + plane_off(n, k)) = make_uint2(h0, h1);
    } else if (idx < 81920 + 1536) {
        int rem = idx - 81920;
        int row = rem >> 5;
        int k = (rem & 31) * 4;
        float w[4];
#pragma unroll
        for (int i = 0; i < 4; i++) {
            int kk = k + i;
            w[i] = (row < 32) ? __ldg(Wc1 + kk * 32 + row) : (row == 32 ? __ldg(Ws1 + kk) : 0.f);
        }
        *(uint2*)(g_ax + plane_off(row, k)) =
            make_uint2(pack_h(w[0], w[1]), pack_h(w[2], w[3]));
    }
}

// ======================= main kernel =======================
extern "C" __global__ void __launch_bounds__(256, 2)
qatten_mma(const float* __restrict__ states,
           const float* __restrict__ b1, const float* __restrict__ b2,
           const float* __restrict__ b3,
           const float* __restrict__ bs1, const float* __restrict__ Ws2,
           const float* __restrict__ bs2,
           const float* __restrict__ bc1, const float* __restrict__ Wc2,
           const float* __restrict__ bc2,
           float* __restrict__ out)
{
    extern __shared__ char smem[];
    const u32 sb = smem_u32(smem);
    const int tid = threadIdx.x;
    const int wid = tid >> 5, lane = tid & 31;
    const int b0 = blockIdx.x * BM;

    const int mq = wid & 1, nw = wid >> 1;   // 2 M-slices x 4 N-slices
    const int m0 = mq * 32;
    const int q = (lane & 3) * 2;

    float* sG  = (float*)(smem + SGOFF);
    float* sRd = (float*)(smem + SREDO);

    // ---- prologue: stage states(0) -> RST; W1(0) + aux -> RW ----
    {
        const unsigned char* S0 = (const unsigned char*)(states + (size_t)b0 * 128);
        for (int i = tid * 16; i < 32768; i += 4096) cp16(sb + RST + i, S0 + i);
        cp_commit();                                        // [S]
        for (int i = tid * 16; i < 32768; i += 4096) cp16(sb + RW + i, g_w + i);
        for (int i = tid * 16; i < 12288; i += 4096) cp16(sb + RW + 32768 + i, g_ax + i);
        cp_commit();                                        // [S, W1]
    }

    float oacc[2][2][4];
#pragma unroll
    for (int mf = 0; mf < 2; mf++)
#pragma unroll
        for (int j = 0; j < 2; j++)
#pragma unroll
            for (int i = 0; i < 4; i++) oacc[mf][j][i] = 0.f;
    float creg[4] = {0.f, 0.f, 0.f, 0.f};
    const float r_bs1 = __ldg(bs1), r_Ws2 = __ldg(Ws2), r_bs2 = __ldg(bs2), r_bc2 = __ldg(bc2);

    for (int n = 0; n < NAGENT; n++) {
        // ---- convert staged f32 states -> RA fp16 plane ----
        cp_wait<1>();               // states ready (weight group may be pending)
        __syncthreads();            // prev agent's L3 done with RA
#pragma unroll
        for (int i = 0; i < 8; i++) {
            int idx = tid + 256 * i;
            int m = idx >> 5, c4 = idx & 31;
            float4 v;
            asm volatile("ld.shared.v4.f32 {%0,%1,%2,%3}, [%4];"
                : "=f"(v.x), "=f"(v.y), "=f"(v.z), "=f"(v.w)
                : "r"(sb + RST + m * 512 + c4 * 16));
            u32 h0 = pack_h(v.x, v.y);
            u32 h1 = pack_h(v.z, v.w);
            asm volatile("st.shared.v2.b32 [%0], {%1,%2};"
                :: "r"(sb + RA + plane_off(m, c4 * 4)), "r"(h0), "r"(h1));
        }
        cp_wait<0>();               // W1 ready
        __syncthreads();

        // ---- L1 + aux: RA @ [W1 ; Wc1^T ; Ws1]  (N=176, tiles 0..21, 21=pad) ----
        {
            const float* b1n = b1 + n * 128;
            if (nw < 2) {
                float C[2][6][4];
                gemm2m<6>(C, sb + RA, sb + RW, m0, nw * 6, lane);
                __syncthreads();    // RW consumed; RST consumed
                {   // stream W2 while epilogue runs
                    const unsigned char* src = g_w + (size_t)n * 81920 + 32768;
                    for (int i = tid * 16; i < 32768; i += 4096) cp16(sb + RW + i, src + i);
                    cp_commit();
                }
                if (nw == 0)
                    epi_L1<6, 0>(C, sb, b1n, bc1, Wc2, r_bs1, r_Ws2, r_bs2, r_bc2,
                                 sG, sRd, creg, m0, lane, q);
                else
                    epi_L1<6, 6>(C, sb, b1n, bc1, Wc2, r_bs1, r_Ws2, r_bs2, r_bc2,
                                 sG, sRd, creg, m0, lane, q);
            } else {
                float C[2][5][4];
                gemm2m<5>(C, sb + RA, sb + RW, m0, (nw == 2) ? 12 : 17, lane);
                __syncthreads();
                {
                    const unsigned char* src = g_w + (size_t)n * 81920 + 32768;
                    for (int i = tid * 16; i < 32768; i += 4096) cp16(sb + RW + i, src + i);
                    cp_commit();
                }
                if (nw == 2)
                    epi_L1<5, 12>(C, sb, b1n, bc1, Wc2, r_bs1, r_Ws2, r_bs2, r_bc2,
                                  sG, sRd, creg, m0, lane, q);
                else
                    epi_L1<5, 17>(C, sb, b1n, bc1, Wc2, r_bs1, r_Ws2, r_bs2, r_bc2,
                                  sG, sRd, creg, m0, lane, q);
            }
        }
        cp_wait<0>();
        __syncthreads();

        // ---- L2: RB @ W2 (N=128, tiles nw*4+j) -> RA plane ----
        {
            float C[2][4][4];
            gemm2m<4>(C, sb + RB, sb + RW, m0, nw * 4, lane);
            __syncthreads();        // RW, RB consumed
            {   // stream W3 + states(n+1)
                const unsigned char* src = g_w + (size_t)n * 81920 + 65536;
                for (int i = tid * 16; i < 16384; i += 4096) cp16(sb + RW + i, src + i);
                cp_commit();        // [W3]
                if (n < NAGENT - 1) {
                    const unsigned char* Sn =
                        (const unsigned char*)(states + ((size_t)(n + 1) * BATCH + b0) * 128);
                    for (int i = tid * 16; i < 32768; i += 4096) cp16(sb + RST + i, Sn + i);
                }
                cp_commit();        // [W3, S']
            }
            const float* b2n = b2 + n * 128;
#pragma unroll
            for (int j = 0; j < 4; j++) {
                int tile = nw * 4 + j;
                int col = tile * 8 + q;
                float bx = __ldg(b2n + col), by = __ldg(b2n + col + 1);
#pragma unroll
                for (int mf = 0; mf < 2; mf++) {
                    int row0 = m0 + mf * 16 + (lane >> 2), row8 = row0 + 8;
                    u32 h0 = pack_h(fmaxf(C[mf][j][0] + bx, 0.f), fmaxf(C[mf][j][1] + by, 0.f));
                    u32 h2 = pack_h(fmaxf(C[mf][j][2] + bx, 0.f), fmaxf(C[mf][j][3] + by, 0.f));
                    u32 sw0 = ((u32)(((tile ^ row0) & 7) | (tile & 8))) << 4;
                    u32 sw8 = ((u32)(((tile ^ row8) & 7) | (tile & 8))) << 4;
                    asm volatile("st.shared.b32 [%0], %1;"
                        :: "r"(sb + RA + (u32)row0 * 256 + sw0 + (u32)(q * 2)), "r"(h0));
                    asm volatile("st.shared.b32 [%0], %1;"
                        :: "r"(sb + RA + (u32)row8 * 256 + sw8 + (u32)(q * 2)), "r"(h2));
                }
            }
        }
        cp_wait<1>();               // W3 ready (states still streaming)
        __syncthreads();

        // ---- L3: RA @ W3 (N=64, tiles nw*2+j) -> oacc ----
        {
            float C[2][2][4];
            gemm2m<2>(C, sb + RA, sb + RW, m0, nw * 2, lane);
            __syncthreads();        // RA, RW consumed
            if (n < NAGENT - 1) {   // stream W1(n+1)  (aux rows persist)
                const unsigned char* src = g_w + (size_t)(n + 1) * 81920;
                for (int i = tid * 16; i < 32768; i += 4096) cp16(sb + RW + i, src + i);
            }
            cp_commit();            // [S', W1']
            const float* b3n = b3 + n * 64;
#pragma unroll
            for (int mf = 0; mf < 2; mf++) {
                int row0 = m0 + mf * 16 + (lane >> 2), row8 = row0 + 8;
                float g0 = sG[row0], g8 = sG[row8];
#pragma unroll
                for (int j = 0; j < 2; j++) {
                    int col = (nw * 2 + j) * 8 + q;
                    float bx = __ldg(b3n + col), by = __ldg(b3n + col + 1);
                    oacc[mf][j][0] = fmaf(g0, C[mf][j][0] + bx, oacc[mf][j][0]);
                    oacc[mf][j][1] = fmaf(g0, C[mf][j][1] + by, oacc[mf][j][1]);
                    oacc[mf][j][2] = fmaf(g8, C[mf][j][2] + bx, oacc[mf][j][2]);
                    oacc[mf][j][3] = fmaf(g8, C[mf][j][3] + by, oacc[mf][j][3]);
                }
            }
        }
    }

    // ---- final: csum exchange + output ----
    if ((nw == 2 || nw == 3) && (lane & 3) == 0) {
        int slot = nw - 2;
#pragma unroll
        for (int i = 0; i < 4; i++) {
            int row = m0 + (i >> 1) * 16 + (i & 1) * 8 + (lane >> 2);
            sRd[row * 2 + slot] = creg[i];
        }
    }
    __syncthreads();
#pragma unroll
    for (int mf = 0; mf < 2; mf++) {
#pragma unroll
        for (int h = 0; h < 2; h++) {
            int row = m0 + mf * 16 + h * 8 + (lane >> 2);
            float cs = (sRd[row * 2] + sRd[row * 2 + 1]) * 0.125f;
#pragma unroll
            for (int j = 0; j < 2; j++) {
                int col = (nw * 2 + j) * 8 + q;
                float2 v;
                v.x = fmaf(oacc[mf][j][2 * h + 0], 0.125f, cs);
                v.y = fmaf(oacc[mf][j][2 * h + 1], 0.125f, cs);
                *(float2*)(out + (size_t)(b0 + row) * 64 + col) = v;
            }
        }
    }
}

extern "C" void kernel_launch(void* const* d_in, const int* in_sizes, int n_in,
                              void* d_out, int out_size)
{
    const float* states = (const float*)d_in[0];
    const float* W1  = (const float*)d_in[1];
    const float* b1  = (const float*)d_in[2];
    const float* W2  = (const float*)d_in[3];
    const float* b2  = (const float*)d_in[4];
    const float* W3  = (const float*)d_in[5];
    const float* b3  = (const float*)d_in[6];
    // d_in[7..12]: Wq1,bq1,Wq2,bq2,Wk,bk — dead (softmax rows sum to 1)
    const float* Ws1 = (const float*)d_in[13];
    const float* bs1 = (const float*)d_in[14];
    const float* Ws2 = (const float*)d_in[15];
    const float* bs2 = (const float*)d_in[16];
    const float* Wc1 = (const float*)d_in[17];
    const float* bc1 = (const float*)d_in[18];
    const float* Wc2 = (const float*)d_in[19];
    const float* bc2 = (const float*)d_in[20];
    float* out = (float*)d_out;

    prep_kernel<<<(81920 + 1536 + 255) / 256, 256>>>(W1, W2, W3, Wc1, Ws1);

    cudaFuncSetAttribute(qatten_mma,
                         cudaFuncAttributeMaxDynamicSharedMemorySize, SMEM_TOTAL);
    qatten_mma<<<BATCH / BM, 256, SMEM_TOTAL>>>(
        states, b1, b2, b3, bs1, Ws2, bs2, bc1, Wc2, bc2, out);
}

// round 11
// speedup vs baseline: 6.7535x; 1.0085x over previous
#include <cuda_runtime.h>
#include <cuda_fp16.h>
#include <cstdint>

typedef unsigned u32;

#define NAGENT 8
#define BATCH  32768
#define BM     64

// ---- scratch: pre-swizzled fp16 weights ----
// per agent: L1 (128 rows) off 0, L2 off 32768, L3 (64 rows) off 65536; stride 81920
__device__ __align__(16) unsigned char g_w[8 * 81920];
__device__ __align__(16) unsigned char g_ax[48 * 256];   // aux: Wc1^T rows 0-31, Ws1 row 32, pad

// ---- smem byte offsets (per CTA, ~109 KB -> 2 CTAs/SM) ----
#define RA    0          // plane P0: 64 rows x 256B fp16
#define RB    16384      // plane P1
#define RST   32768      // f32 states staging (64 x 512B = 32KB)
#define RW    65536      // weights, 176 rows x 256B = 45056 (aux rows 128-175 persist)
#define SGOFF 110592     // gate per row (64 f32)
#define SREDO 110848     // csum partials (64 rows x 2 slots)
#define SMEM_TOTAL 111616

// ======================= helpers =======================
__device__ __forceinline__ u32 smem_u32(const void* p) {
    u32 a; asm("{ .reg .u64 t; cvta.to.shared.u64 t, %1; cvt.u32.u64 %0, t; }" : "=r"(a) : "l"(p));
    return a;
}
__device__ __forceinline__ void cp16(u32 dst, const void* src) {
    asm volatile("cp.async.cg.shared.global [%0], [%1], 16;" :: "r"(dst), "l"(src));
}
__device__ __forceinline__ void cp_commit() { asm volatile("cp.async.commit_group;"); }
template<int N> __device__ __forceinline__ void cp_wait() {
    asm volatile("cp.async.wait_group %0;" :: "n"(N) : "memory");
}
__device__ __forceinline__ u32 pack_h(float x, float y) {
    __half2 h = __floats2half2_rn(x, y);
    return *reinterpret_cast<u32*>(&h);
}
// plane byte offset: row n, half-col k; 256B rows, XOR swizzle on 16B chunks
__device__ __forceinline__ u32 plane_off(int n, int k) {
    int c = k >> 3;
    u32 sw = (u32)(((c ^ n) & 7) | (c & 8));
    return (u32)(n * 256) + (sw << 4) + (u32)((k & 7) * 2);
}
__device__ __forceinline__ void ldm4(u32* a, u32 addr) {
    asm volatile("ldmatrix.sync.aligned.m8n8.x4.shared.b16 {%0,%1,%2,%3}, [%4];"
        : "=r"(a[0]), "=r"(a[1]), "=r"(a[2]), "=r"(a[3]) : "r"(addr));
}
__device__ __forceinline__ void ldm2(u32* b, u32 addr) {
    asm volatile("ldmatrix.sync.aligned.m8n8.x2.shared.b16 {%0,%1}, [%2];"
        : "=r"(b[0]), "=r"(b[1]) : "r"(addr));
}
__device__ __forceinline__ void mma_h(float* d, const u32* a, const u32* b) {
    asm volatile("mma.sync.aligned.m16n8k16.row.col.f32.f16.f16.f32 "
        "{%0,%1,%2,%3}, {%4,%5,%6,%7}, {%8,%9}, {%0,%1,%2,%3};"
        : "+f"(d[0]), "+f"(d[1]), "+f"(d[2]), "+f"(d[3])
        : "r"(a[0]), "r"(a[1]), "r"(a[2]), "r"(a[3]), "r"(b[0]), "r"(b[1]));
}

// convert own-copied f32 chunks (RST) -> fp16 plane. Each thread touches exactly
// the bytes it cp.async'd (same tid*16 + 4096j mapping) => only own-group wait needed.
__device__ __forceinline__ void convert_own(u32 sb, u32 dst, int tid) {
#pragma unroll
    for (int j = 0; j < 8; j++) {
        int o = tid * 16 + 4096 * j;
        int m = o >> 9, c4 = (o & 511) >> 4;
        float4 v;
        asm volatile("ld.shared.v4.f32 {%0,%1,%2,%3}, [%4];"
            : "=f"(v.x), "=f"(v.y), "=f"(v.z), "=f"(v.w) : "r"(sb + RST + o));
        u32 h0 = pack_h(v.x, v.y);
        u32 h1 = pack_h(v.z, v.w);
        asm volatile("st.shared.v2.b32 [%0], {%1,%2};"
            :: "r"(dst + plane_off(m, c4 * 4)), "r"(h0), "r"(h1));
    }
}

// ============ warp GEMM: 32 M-rows (MF=2), NF n8-tiles, paired x4 B loads ============
template<int NF>
__device__ __forceinline__ void gemm2m(float C[2][NF][4], u32 ah, u32 bw,
                                       int m0, int tbase, int lane)
{
#pragma unroll
    for (int mf = 0; mf < 2; mf++)
#pragma unroll
        for (int j = 0; j < NF; j++)
#pragma unroll
            for (int i = 0; i < 4; i++) C[mf][j][i] = 0.f;

    const int rA = m0 + (lane & 7) + ((lane >> 3) & 1) * 8;
    const int gA = lane >> 4;
    const u32 oA = (u32)rA * 256;
    const int rBl = lane & 7;
    const int gB = (lane >> 3) & 1;
    const int tsel = (lane >> 4) & 1;

#pragma unroll
    for (int t = 0; t < 8; t++) {
        const int cA = 2 * t + gA;
        const u32 swA = ((u32)(((cA ^ rA) & 7) | (cA & 8))) << 4;
        u32 A0[4], A1[4];
        ldm4(A0, ah + oA + swA);            // rows m0..m0+15
        ldm4(A1, ah + oA + 4096 + swA);     // rows m0+16..m0+31

        const int cB = 2 * t + gB;
#pragma unroll
        for (int jp = 0; jp < NF / 2; jp++) {
            int tile = tbase + 2 * jp + tsel;
            int rB = tile * 8 + rBl;
            u32 swB = ((u32)(((cB ^ rB) & 7) | (cB & 8))) << 4;
            u32 B4[4];
            ldm4(B4, bw + (u32)rB * 256 + swB);
            mma_h(C[0][2 * jp],     A0, B4);
            mma_h(C[0][2 * jp + 1], A0, B4 + 2);
            mma_h(C[1][2 * jp],     A1, B4);
            mma_h(C[1][2 * jp + 1], A1, B4 + 2);
        }
        if (NF & 1) {
            int tile = tbase + NF - 1;
            int rB = tile * 8 + rBl;
            u32 swB = ((u32)(((cB ^ rB) & 7) | (cB & 8))) << 4;
            u32 B2[2];
            ldm2(B2, bw + (u32)rB * 256 + swB);
            mma_h(C[0][NF - 1], A0, B2);
            mma_h(C[1][NF - 1], A1, B2);
        }
    }
}

// ======================= L1 epilogue (activation stores to dst + aux) =======================
template<int NF, int TBASE>
__device__ __forceinline__ void epi_L1(float C[2][NF][4], u32 dst,
    const float* __restrict__ b1n, const float* __restrict__ bc1,
    const float* __restrict__ Wc2,
    float r_bs1, float r_Ws2, float r_bs2, float r_bc2,
    float* sG, float creg[4], int m0, int lane, int q)
{
    float cp[4] = {0.f, 0.f, 0.f, 0.f};
#pragma unroll
    for (int j = 0; j < NF; j++) {
        const int tile = TBASE + j;
        if (tile < 16) {
            int col = tile * 8 + q;
            float bx = __ldg(b1n + col), by = __ldg(b1n + col + 1);
#pragma unroll
            for (int mf = 0; mf < 2; mf++) {
                int row0 = m0 + mf * 16 + (lane >> 2), row8 = row0 + 8;
                u32 h0 = pack_h(fmaxf(C[mf][j][0] + bx, 0.f), fmaxf(C[mf][j][1] + by, 0.f));
                u32 h2 = pack_h(fmaxf(C[mf][j][2] + bx, 0.f), fmaxf(C[mf][j][3] + by, 0.f));
                u32 sw0 = ((u32)(((tile ^ row0) & 7) | (tile & 8))) << 4;
                u32 sw8 = ((u32)(((tile ^ row8) & 7) | (tile & 8))) << 4;
                asm volatile("st.shared.b32 [%0], %1;"
                    :: "r"(dst + (u32)row0 * 256 + sw0 + (u32)(q * 2)), "r"(h0));
                asm volatile("st.shared.b32 [%0], %1;"
                    :: "r"(dst + (u32)row8 * 256 + sw8 + (u32)(q * 2)), "r"(h2));
            }
        } else if (tile < 20) {     // constraint cols: e in [0,32)
            int e = (tile - 16) * 8 + q;
            float bb0 = __ldg(bc1 + e),  bb1 = __ldg(bc1 + e + 1);
            float w0  = __ldg(Wc2 + e),  w1  = __ldg(Wc2 + e + 1);
#pragma unroll
            for (int mf = 0; mf < 2; mf++) {
                cp[mf * 2 + 0] = fmaf(fmaxf(C[mf][j][0] + bb0, 0.f), w0,
                                 fmaf(fmaxf(C[mf][j][1] + bb1, 0.f), w1, cp[mf * 2 + 0]));
                cp[mf * 2 + 1] = fmaf(fmaxf(C[mf][j][2] + bb0, 0.f), w0,
                                 fmaf(fmaxf(C[mf][j][3] + bb1, 0.f), w1, cp[mf * 2 + 1]));
            }
        } else if (tile == 20) {    // gate col (e==32) at q==0
            if (q == 0) {
#pragma unroll
                for (int mf = 0; mf < 2; mf++) {
                    int row0 = m0 + mf * 16 + (lane >> 2), row8 = row0 + 8;
                    float s0 = fmaf(fmaxf(C[mf][j][0] + r_bs1, 0.f), r_Ws2, r_bs2);
                    float s8 = fmaf(fmaxf(C[mf][j][2] + r_bs1, 0.f), r_Ws2, r_bs2);
                    sG[row0] = 1.f / (1.f + __expf(-s0));
                    sG[row8] = 1.f / (1.f + __expf(-s8));
                }
            }
        }
        // tile 21: zero padding, skip
    }
    if (TBASE >= 12) {              // constraint-carrying warps (nw 2,3)
#pragma unroll
        for (int i = 0; i < 4; i++) {
            cp[i] += __shfl_xor_sync(0xffffffffu, cp[i], 1);
            cp[i] += __shfl_xor_sync(0xffffffffu, cp[i], 2);
        }
        if ((lane & 3) == 0) {
            float add = (TBASE == 12) ? r_bc2 : 0.f;
#pragma unroll
            for (int i = 0; i < 4; i++) creg[i] += cp[i] + add;
        }
    }
}

// ======================= prep kernel: fp32 weights -> swizzled fp16 =======================
extern "C" __global__ void __launch_bounds__(256)
prep_kernel(const float* __restrict__ W1, const float* __restrict__ W2,
            const float* __restrict__ W3, const float* __restrict__ Wc1,
            const float* __restrict__ Ws1)
{
    int idx = blockIdx.x * 256 + threadIdx.x;
    if (idx < 81920) {
        int agent = idx / 10240;
        int rem = idx % 10240;
        int row = rem >> 5;
        int k = (rem & 31) * 4;
        const float* src; int n, N; u32 loff;
        if (row < 128)      { src = W1 + agent * 16384; n = row;       N = 128; loff = 0; }
        else if (row < 256) { src = W2 + agent * 16384; n = row - 128; N = 128; loff = 32768; }
        else                { src = W3 + agent * 8192;  n = row - 256; N = 64;  loff = 65536; }
        u32 h0 = pack_h(src[(k + 0) * N + n], src[(k + 1) * N + n]);
        u32 h1 = pack_h(src[(k + 2) * N + n], src[(k + 3) * N + n]);
        *(uint2*)(g_w + (u32)agent * 81920 + loff + plane_off(n, k)) = make_uint2(h0, h1);
    } else if (idx < 81920 + 1536) {
        int rem = idx - 81920;
        int row = rem >> 5;
        int k = (rem & 31) * 4;
        float w[4];
#pragma unroll
        for (int i = 0; i < 4; i++) {
            int kk = k + i;
            w[i] = (row < 32) ? __ldg(Wc1 + kk * 32 + row) : (row == 32 ? __ldg(Ws1 + kk) : 0.f);
        }
        *(uint2*)(g_ax + plane_off(row, k)) =
            make_uint2(pack_h(w[0], w[1]), pack_h(w[2], w[3]));
    }
}

// ======================= main kernel =======================
extern "C" __global__ void __launch_bounds__(256, 2)
qatten_mma(const float* __restrict__ states,
           const float* __restrict__ b1, const float* __restrict__ b2,
           const float* __restrict__ b3,
           const float* __restrict__ bs1, const float* __restrict__ Ws2,
           const float* __restrict__ bs2,
           const float* __restrict__ bc1, const float* __restrict__ Wc2,
           const float* __restrict__ bc2,
           float* __restrict__ out)
{
    extern __shared__ char smem[];
    const u32 sb = smem_u32(smem);
    const int tid = threadIdx.x;
    const int wid = tid >> 5, lane = tid & 31;
    const int b0 = blockIdx.x * BM;

    const int mq = wid & 1, nw = wid >> 1;   // 2 M-slices x 4 N-slices
    const int m0 = mq * 32;
    const int q = (lane & 3) * 2;

    float* sG  = (float*)(smem + SGOFF);
    float* sRd = (float*)(smem + SREDO);

    // ---- prologue: stage states(0) -> RST; W1(0)+aux -> RW; convert(0) -> P0 ----
    {
        const unsigned char* S0 = (const unsigned char*)(states + (size_t)b0 * 128);
        for (int i = tid * 16; i < 32768; i += 4096) cp16(sb + RST + i, S0 + i);
        cp_commit();                                        // [S]
        for (int i = tid * 16; i < 32768; i += 4096) cp16(sb + RW + i, g_w + i);
        for (int i = tid * 16; i < 12288; i += 4096) cp16(sb + RW + 32768 + i, g_ax + i);
        cp_commit();                                        // [S, W1]
        cp_wait<1>();                // own states chunks done (W1 outstanding)
        convert_own(sb, sb + RA, tid);   // states(0) -> P0
    }

    float oacc[2][2][4];
#pragma unroll
    for (int mf = 0; mf < 2; mf++)
#pragma unroll
        for (int j = 0; j < 2; j++)
#pragma unroll
            for (int i = 0; i < 4; i++) oacc[mf][j][i] = 0.f;
    float creg[4] = {0.f, 0.f, 0.f, 0.f};
    const float r_bs1 = __ldg(bs1), r_Ws2 = __ldg(Ws2), r_bs2 = __ldg(bs2), r_bc2 = __ldg(bc2);

    for (int n = 0; n < NAGENT; n++) {
        const u32 pin  = sb + ((n & 1) ? RB : RA);   // L1 input (states), L2 output, L3 input
        const u32 pmid = sb + ((n & 1) ? RA : RB);   // L1 output, L2 input, convert(n+1) dest

        // ---- L1 phase: weights ready + all prior smem writes visible ----
        cp_wait<0>();
        __syncthreads();
        {
            const float* b1n = b1 + n * 128;
            if (nw < 2) {
                float C[2][6][4];
                gemm2m<6>(C, pin, sb + RW, m0, nw * 6, lane);
                __syncthreads();    // pin + RW consumed
                {   // stream W2 while epilogue runs
                    const unsigned char* src = g_w + (size_t)n * 81920 + 32768;
                    for (int i = tid * 16; i < 32768; i += 4096) cp16(sb + RW + i, src + i);
                    cp_commit();    // [W2]
                }
                if (nw == 0)
                    epi_L1<6, 0>(C, pmid, b1n, bc1, Wc2, r_bs1, r_Ws2, r_bs2, r_bc2,
                                 sG, creg, m0, lane, q);
                else
                    epi_L1<6, 6>(C, pmid, b1n, bc1, Wc2, r_bs1, r_Ws2, r_bs2, r_bc2,
                                 sG, creg, m0, lane, q);
            } else {
                float C[2][5][4];
                gemm2m<5>(C, pin, sb + RW, m0, (nw == 2) ? 12 : 17, lane);
                __syncthreads();
                {
                    const unsigned char* src = g_w + (size_t)n * 81920 + 32768;
                    for (int i = tid * 16; i < 32768; i += 4096) cp16(sb + RW + i, src + i);
                    cp_commit();    // [W2]
                }
                if (nw == 2)
                    epi_L1<5, 12>(C, pmid, b1n, bc1, Wc2, r_bs1, r_Ws2, r_bs2, r_bc2,
                                  sG, creg, m0, lane, q);
                else
                    epi_L1<5, 17>(C, pmid, b1n, bc1, Wc2, r_bs1, r_Ws2, r_bs2, r_bc2,
                                  sG, creg, m0, lane, q);
            }
        }
        cp_wait<0>();
        __syncthreads();

        // ---- L2: pmid @ W2 -> pin ----
        {
            float C[2][4][4];
            gemm2m<4>(C, pmid, sb + RW, m0, nw * 4, lane);
            __syncthreads();        // pmid + RW consumed
            {   // stream W3 + states(n+1)
                const unsigned char* src = g_w + (size_t)n * 81920 + 65536;
                for (int i = tid * 16; i < 16384; i += 4096) cp16(sb + RW + i, src + i);
                cp_commit();        // [W3]
                if (n < NAGENT - 1) {
                    const unsigned char* Sn =
                        (const unsigned char*)(states + ((size_t)(n + 1) * BATCH + b0) * 128);
                    for (int i = tid * 16; i < 32768; i += 4096) cp16(sb + RST + i, Sn + i);
                }
                cp_commit();        // [W3, S'] (S' empty at n=7; keeps group count)
            }
            const float* b2n = b2 + n * 128;
#pragma unroll
            for (int j = 0; j < 4; j++) {
                int tile = nw * 4 + j;
                int col = tile * 8 + q;
                float bx = __ldg(b2n + col), by = __ldg(b2n + col + 1);
#pragma unroll
                for (int mf = 0; mf < 2; mf++) {
                    int row0 = m0 + mf * 16 + (lane >> 2), row8 = row0 + 8;
                    u32 h0 = pack_h(fmaxf(C[mf][j][0] + bx, 0.f), fmaxf(C[mf][j][1] + by, 0.f));
                    u32 h2 = pack_h(fmaxf(C[mf][j][2] + bx, 0.f), fmaxf(C[mf][j][3] + by, 0.f));
                    u32 sw0 = ((u32)(((tile ^ row0) & 7) | (tile & 8))) << 4;
                    u32 sw8 = ((u32)(((tile ^ row8) & 7) | (tile & 8))) << 4;
                    asm volatile("st.shared.b32 [%0], %1;"
                        :: "r"(pin + (u32)row0 * 256 + sw0 + (u32)(q * 2)), "r"(h0));
                    asm volatile("st.shared.b32 [%0], %1;"
                        :: "r"(pin + (u32)row8 * 256 + sw8 + (u32)(q * 2)), "r"(h2));
                }
            }
        }
        cp_wait<1>();               // W3 ready (S' may be outstanding)
        __syncthreads();

        // ---- L3: pin @ W3 -> oacc ; convert(n+1) -> pmid hides under the gemm ----
        {
            float C[2][2][4];
            gemm2m<2>(C, pin, sb + RW, m0, nw * 2, lane);
            if (n < NAGENT - 1) {
                cp_wait<0>();               // own states(n+1) chunks done
                convert_own(sb, pmid, tid); // pmid free (L2 consumed it)
            }
            const float* b3n = b3 + n * 64;
#pragma unroll
            for (int mf = 0; mf < 2; mf++) {
                int row0 = m0 + mf * 16 + (lane >> 2), row8 = row0 + 8;
                float g0 = sG[row0], g8 = sG[row8];
#pragma unroll
                for (int j = 0; j < 2; j++) {
                    int col = (nw * 2 + j) * 8 + q;
                    float bx = __ldg(b3n + col), by = __ldg(b3n + col + 1);
                    oacc[mf][j][0] = fmaf(g0, C[mf][j][0] + bx, oacc[mf][j][0]);
                    oacc[mf][j][1] = fmaf(g0, C[mf][j][1] + by, oacc[mf][j][1]);
                    oacc[mf][j][2] = fmaf(g8, C[mf][j][2] + bx, oacc[mf][j][2]);
                    oacc[mf][j][3] = fmaf(g8, C[mf][j][3] + by, oacc[mf][j][3]);
                }
            }
            __syncthreads();        // pin + RW consumed; convert visible
            if (n < NAGENT - 1) {   // stream W1(n+1) (aux rows persist)
                const unsigned char* src = g_w + (size_t)(n + 1) * 81920;
                for (int i = tid * 16; i < 32768; i += 4096) cp16(sb + RW + i, src + i);
                cp_commit();        // [W1']
            }
        }
    }

    // ---- final: csum exchange + output ----
    if ((nw == 2 || nw == 3) && (lane & 3) == 0) {
        int slot = nw - 2;
#pragma unroll
        for (int i = 0; i < 4; i++) {
            int row = m0 + (i >> 1) * 16 + (i & 1) * 8 + (lane >> 2);
            sRd[row * 2 + slot] = creg[i];
        }
    }
    __syncthreads();
#pragma unroll
    for (int mf = 0; mf < 2; mf++) {
#pragma unroll
        for (int h = 0; h < 2; h++) {
            int row = m0 + mf * 16 + h * 8 + (lane >> 2);
            float cs = (sRd[row * 2] + sRd[row * 2 + 1]) * 0.125f;
#pragma unroll
            for (int j = 0; j < 2; j++) {
                int col = (nw * 2 + j) * 8 + q;
                float2 v;
                v.x = fmaf(oacc[mf][j][2 * h + 0], 0.125f, cs);
                v.y = fmaf(oacc[mf][j][2 * h + 1], 0.125f, cs);
                *(float2*)(out + (size_t)(b0 + row) * 64 + col) = v;
            }
        }
    }
}

extern "C" void kernel_launch(void* const* d_in, const int* in_sizes, int n_in,
                              void* d_out, int out_size)
{
    const float* states = (const float*)d_in[0];
    const float* W1  = (const float*)d_in[1];
    const float* b1  = (const float*)d_in[2];
    const float* W2  = (const float*)d_in[3];
    const float* b2  = (const float*)d_in[4];
    const float* W3  = (const float*)d_in[5];
    const float* b3  = (const float*)d_in[6];
    // d_in[7..12]: Wq1,bq1,Wq2,bq2,Wk,bk — dead (softmax rows sum to 1)
    const float* Ws1 = (const float*)d_in[13];
    const float* bs1 = (const float*)d_in[14];
    const float* Ws2 = (const float*)d_in[15];
    const float* bs2 = (const float*)d_in[16];
    const float* Wc1 = (const float*)d_in[17];
    const float* bc1 = (const float*)d_in[18];
    const float* Wc2 = (const float*)d_in[19];
    const float* bc2 = (const float*)d_in[20];
    float* out = (float*)d_out;

    prep_kernel<<<(81920 + 1536 + 255) / 256, 256>>>(W1, W2, W3, Wc1, Ws1);

    cudaFuncSetAttribute(qatten_mma,
                         cudaFuncAttributeMaxDynamicSharedMemorySize, SMEM_TOTAL);
    qatten_mma<<<BATCH / BM, 256, SMEM_TOTAL>>>(
        states, b1, b2, b3, bs1, Ws2, bs2, bc1, Wc2, bc2, out);
}